// round 1
// baseline (speedup 1.0000x reference)
#include <cuda_runtime.h>
#include <math.h>

#define N_NODES 16000
#define N_EDGES 64000
#define HH 90
#define F0 16
#define EF 8
#define NGR 512
#define H2 45
#define CAP 64

// ---------------- scratch (__device__ globals; no allocation) ----------------
__device__ float g_X0[N_NODES * F0];
__device__ float g_bufA[N_NODES * HH];
__device__ float g_bufB[N_NODES * HH];
__device__ float g_h[N_EDGES * HH];
__device__ float g_G[(size_t)N_NODES * HH * HH];   // 518 MB max
__device__ float g_W2g[HH * HH * HH];
__device__ float g_xb[N_NODES * HH];
__device__ float g_agg[N_NODES * HH];
__device__ float g_pool[NGR * H2];
__device__ int   g_deg[N_NODES];
__device__ int   g_bucket[N_NODES * CAP];
__device__ int   g_ovf[N_EDGES];
__device__ int   g_ovfn;

// ---------------- small utility kernels ----------------
__global__ void zero_f(float* p, int n) {
    int i = blockIdx.x * blockDim.x + threadIdx.x;
    if (i < n) p[i] = 0.f;
}

__global__ void init_deg() {
    int i = blockIdx.x * blockDim.x + threadIdx.x;
    if (i < N_NODES) g_deg[i] = 0;
    if (i == 0) g_ovfn = 0;
}

__global__ void build_x0(const float* __restrict__ x, const float* __restrict__ pos) {
    int i = blockIdx.x * blockDim.x + threadIdx.x;
    if (i >= N_NODES * F0) return;
    int n = i / F0, c = i % F0;
    g_X0[i] = (c < 13) ? x[n * 13 + c] : pos[n * 3 + (c - 13)];
}

__global__ void bucket_build(const int* __restrict__ ei) {
    int e = blockIdx.x * blockDim.x + threadIdx.x;
    if (e >= N_EDGES) return;
    int s = ei[e];
    int slot = atomicAdd(&g_deg[s], 1);
    if (slot < CAP) g_bucket[s * CAP + slot] = e;
    else            g_ovf[atomicAdd(&g_ovfn, 1)] = e;
}

// h[e,:] = relu(edge_attr[e,:] @ w1 + b1)
__global__ void edge_mlp(const float* __restrict__ ea, const float* __restrict__ w1,
                         const float* __restrict__ b1, float* __restrict__ h) {
    int idx = blockIdx.x * blockDim.x + threadIdx.x;
    if (idx >= N_EDGES * HH) return;
    int e = idx / HH, o = idx % HH;
    float s = b1[o];
#pragma unroll
    for (int j = 0; j < EF; j++) s = fmaf(ea[e * EF + j], w1[j * HH + o], s);
    h[idx] = fmaxf(s, 0.f);
}

// W2g[i][k*out+o] = w2[k][i*out+o]   (permute so G = X @ W2g)
__global__ void permW2(const float* __restrict__ w2, float* __restrict__ W2g,
                       int in_c, int out_c) {
    int idx = blockIdx.x * blockDim.x + threadIdx.x;
    int tot = in_c * HH * out_c;
    if (idx >= tot) return;
    int o = idx % out_c;
    int k = (idx / out_c) % HH;
    int i = idx / (out_c * HH);
    W2g[idx] = w2[(size_t)k * in_c * out_c + i * out_c + o];
}

// ---------------- fp32 GEMM: C[M x Ncols] = A[M x K] @ B[K x Ncols], K<=90, M%64==0 ----------------
__global__ void gemm64(const float* __restrict__ A, const float* __restrict__ B,
                       float* __restrict__ C, int M, int Ncols, int K) {
    __shared__ float As[HH][68];   // [k][row]
    __shared__ float Bs[HH][68];   // [k][col]
    int tid = threadIdx.x;
    int rowBase = blockIdx.y * 64;
    int colBase = blockIdx.x * 64;

    for (int i = tid; i < 64 * K; i += 256) {
        int r = i / K, k = i - r * K;
        As[k][r] = A[(size_t)(rowBase + r) * K + k];
    }
    for (int i = tid; i < 64 * K; i += 256) {
        int c = i & 63, k = i >> 6;
        int col = colBase + c;
        Bs[k][c] = (col < Ncols) ? B[(size_t)k * Ncols + col] : 0.f;
    }
    __syncthreads();

    int tx = tid & 15, ty = tid >> 4;
    int r0 = ty * 4, c0 = tx * 4;
    float acc[4][4];
#pragma unroll
    for (int i = 0; i < 4; i++)
#pragma unroll
        for (int j = 0; j < 4; j++) acc[i][j] = 0.f;

#pragma unroll 5
    for (int k = 0; k < K; k++) {
        float4 a = *(const float4*)(&As[k][r0]);
        float4 b = *(const float4*)(&Bs[k][c0]);
        float av[4] = {a.x, a.y, a.z, a.w};
        float bv[4] = {b.x, b.y, b.z, b.w};
#pragma unroll
        for (int i = 0; i < 4; i++)
#pragma unroll
            for (int j = 0; j < 4; j++)
                acc[i][j] = fmaf(av[i], bv[j], acc[i][j]);
    }

#pragma unroll
    for (int i = 0; i < 4; i++) {
        int row = rowBase + r0 + i;
#pragma unroll
        for (int j = 0; j < 4; j++) {
            int col = colBase + c0 + j;
            if (col < Ncols) C[(size_t)row * Ncols + col] = acc[i][j];
        }
    }
}

// ---------------- per-src-node message + scatter to dst ----------------
__global__ void msg_kernel(const int* __restrict__ ei, int out_c,
                           const float* __restrict__ G, const float* __restrict__ xb,
                           float* __restrict__ agg, const float* __restrict__ h) {
    int n = blockIdx.x;
    int d = g_deg[n];
    if (d == 0) return;
    if (d > CAP) d = CAP;
    __shared__ float hs[HH];
    const float* Grow = &G[(size_t)n * HH * out_c];
    int o = threadIdx.x;
    float xbv = (o < out_c) ? xb[n * out_c + o] : 0.f;
    for (int j = 0; j < d; j++) {
        int e = g_bucket[n * CAP + j];
        for (int t = threadIdx.x; t < HH; t += blockDim.x) hs[t] = h[e * HH + t];
        __syncthreads();
        if (o < out_c) {
            float acc = xbv;
#pragma unroll 6
            for (int k = 0; k < HH; k++) acc = fmaf(hs[k], __ldg(&Grow[k * out_c + o]), acc);
            atomicAdd(&agg[ei[N_EDGES + e] * out_c + o], acc);
        }
        __syncthreads();
    }
}

// fallback for (astronomically unlikely) deg > CAP edges
__global__ void msg_ovf(const int* __restrict__ ei, int out_c,
                        const float* __restrict__ G, const float* __restrict__ xb,
                        float* __restrict__ agg, const float* __restrict__ h) {
    __shared__ float hs[HH];
    for (int idx = blockIdx.x; idx < g_ovfn; idx += gridDim.x) {
        int e = g_ovf[idx];
        int n = ei[e];
        const float* Grow = &G[(size_t)n * HH * out_c];
        for (int t = threadIdx.x; t < HH; t += blockDim.x) hs[t] = h[e * HH + t];
        __syncthreads();
        int o = threadIdx.x;
        if (o < out_c) {
            float acc = xb[n * out_c + o];
            for (int k = 0; k < HH; k++) acc = fmaf(hs[k], Grow[k * out_c + o], acc);
            atomicAdd(&agg[ei[N_EDGES + e] * out_c + o], acc);
        }
        __syncthreads();
    }
}

// out[n,:] = relu(agg[n,:] + Xin[n,:] @ root + bias)
__global__ void finalize_k(const float* __restrict__ Xin, float* __restrict__ Xout,
                           const float* __restrict__ root, const float* __restrict__ bias,
                           const float* __restrict__ agg, int in_c, int out_c) {
    int n = blockIdx.x;
    __shared__ float xs[HH];
    for (int t = threadIdx.x; t < in_c; t += blockDim.x) xs[t] = Xin[n * in_c + t];
    __syncthreads();
    int o = threadIdx.x;
    if (o < out_c) {
        float acc = agg[n * out_c + o] + bias[o];
        for (int i = 0; i < in_c; i++) acc = fmaf(xs[i], __ldg(&root[i * out_c + o]), acc);
        Xout[n * out_c + o] = fmaxf(acc, 0.f);
    }
}

__global__ void pool_add(const int* __restrict__ batch, const float* __restrict__ h3) {
    int idx = blockIdx.x * blockDim.x + threadIdx.x;
    if (idx >= N_NODES * H2) return;
    int n = idx / H2, o = idx % H2;
    atomicAdd(&g_pool[batch[n] * H2 + o], h3[idx]);
}

__global__ void head_k(const float* __restrict__ fc1w, const float* __restrict__ fc1b,
                       const float* __restrict__ outw, const float* __restrict__ outb,
                       float* __restrict__ out) {
    int g = blockIdx.x;
    __shared__ float ps[H2];
    __shared__ float fs[HH];
    for (int t = threadIdx.x; t < H2; t += blockDim.x) ps[t] = g_pool[g * H2 + t];
    __syncthreads();
    int o = threadIdx.x;
    if (o < HH) {
        float a = fc1b[o];
        for (int i = 0; i < H2; i++) a = fmaf(ps[i], fc1w[i * HH + o], a);
        fs[o] = fmaxf(a, 0.f);
    }
    __syncthreads();
    if (threadIdx.x == 0) {
        float s = outb[0];
        for (int q = 0; q < HH; q++) s = fmaf(fs[q], outw[q], s);
        out[g] = s;
    }
}

// ---------------- host orchestration ----------------
static void run_layer(const float* Xin, float* Xout, int in_c, int out_c,
                      const float* w1, const float* b1, const float* w2, const float* b2,
                      const float* root, const float* bias,
                      const float* ea, const int* ei,
                      float* G, float* W2g, float* xb, float* agg, float* h) {
    edge_mlp<<<(N_EDGES * HH + 255) / 256, 256>>>(ea, w1, b1, h);
    permW2<<<(in_c * HH * out_c + 255) / 256, 256>>>(w2, W2g, in_c, out_c);
    {
        dim3 gr((HH * out_c + 63) / 64, N_NODES / 64);
        gemm64<<<gr, 256>>>(Xin, W2g, G, N_NODES, HH * out_c, in_c);
    }
    {
        dim3 gr((out_c + 63) / 64, N_NODES / 64);
        gemm64<<<gr, 256>>>(Xin, b2, xb, N_NODES, out_c, in_c);
    }
    zero_f<<<(N_NODES * out_c + 255) / 256, 256>>>(agg, N_NODES * out_c);
    int bs = ((out_c + 31) / 32) * 32;
    msg_kernel<<<N_NODES, bs>>>(ei, out_c, G, xb, agg, h);
    msg_ovf<<<128, bs>>>(ei, out_c, G, xb, agg, h);
    finalize_k<<<N_NODES, bs>>>(Xin, Xout, root, bias, agg, in_c, out_c);
}

extern "C" void kernel_launch(void* const* d_in, const int* in_sizes, int n_in,
                              void* d_out, int out_size) {
    const float* x    = (const float*)d_in[0];
    const float* pos  = (const float*)d_in[1];
    const float* ea   = (const float*)d_in[2];
    const int*   ei   = (const int*)  d_in[3];
    const int*   bat  = (const int*)  d_in[4];
    const float* c1w1 = (const float*)d_in[5];
    const float* c1b1 = (const float*)d_in[6];
    const float* c1w2 = (const float*)d_in[7];
    const float* c1b2 = (const float*)d_in[8];
    const float* c1r  = (const float*)d_in[9];
    const float* c1b  = (const float*)d_in[10];
    const float* c2w1 = (const float*)d_in[11];
    const float* c2b1 = (const float*)d_in[12];
    const float* c2w2 = (const float*)d_in[13];
    const float* c2b2 = (const float*)d_in[14];
    const float* c2r  = (const float*)d_in[15];
    const float* c2b  = (const float*)d_in[16];
    const float* c3w1 = (const float*)d_in[17];
    const float* c3b1 = (const float*)d_in[18];
    const float* c3w2 = (const float*)d_in[19];
    const float* c3b2 = (const float*)d_in[20];
    const float* c3r  = (const float*)d_in[21];
    const float* c3b  = (const float*)d_in[22];
    const float* f1w  = (const float*)d_in[23];
    const float* f1b  = (const float*)d_in[24];
    const float* ow   = (const float*)d_in[25];
    const float* ob   = (const float*)d_in[26];
    float* out = (float*)d_out;

    void *pX0, *pA, *pB, *pG, *pW2g, *pxb, *pagg, *ph, *ppool;
    cudaGetSymbolAddress(&pX0, g_X0);
    cudaGetSymbolAddress(&pA, g_bufA);
    cudaGetSymbolAddress(&pB, g_bufB);
    cudaGetSymbolAddress(&pG, g_G);
    cudaGetSymbolAddress(&pW2g, g_W2g);
    cudaGetSymbolAddress(&pxb, g_xb);
    cudaGetSymbolAddress(&pagg, g_agg);
    cudaGetSymbolAddress(&ph, g_h);
    cudaGetSymbolAddress(&ppool, g_pool);
    float* X0  = (float*)pX0;
    float* bufA= (float*)pA;
    float* bufB= (float*)pB;
    float* G   = (float*)pG;
    float* W2g = (float*)pW2g;
    float* xb  = (float*)pxb;
    float* agg = (float*)pagg;
    float* h   = (float*)ph;
    float* pool= (float*)ppool;

    build_x0<<<(N_NODES * F0 + 255) / 256, 256>>>(x, pos);
    init_deg<<<(N_NODES + 255) / 256, 256>>>();
    bucket_build<<<(N_EDGES + 255) / 256, 256>>>(ei);

    // layer 1: 16 -> 90
    run_layer(X0, bufA, F0, HH, c1w1, c1b1, c1w2, c1b2, c1r, c1b, ea, ei, G, W2g, xb, agg, h);
    // layer 2: 90 -> 90
    run_layer(bufA, bufB, HH, HH, c2w1, c2b1, c2w2, c2b2, c2r, c2b, ea, ei, G, W2g, xb, agg, h);
    // layer 3: 90 -> 45
    run_layer(bufB, bufA, HH, H2, c3w1, c3b1, c3w2, c3b2, c3r, c3b, ea, ei, G, W2g, xb, agg, h);

    zero_f<<<(NGR * H2 + 255) / 256, 256>>>(pool, NGR * H2);
    pool_add<<<(N_NODES * H2 + 255) / 256, 256>>>(bat, bufA);
    head_k<<<NGR, 96>>>(f1w, f1b, ow, ob, out);
}

// round 2
// speedup vs baseline: 1.4870x; 1.4870x over previous
#include <cuda_runtime.h>
#include <math.h>

#define N_NODES 16000
#define N_EDGES 64000
#define HH 90
#define F0 16
#define EF 8
#define NGR 512
#define H2 45
#define CAP 64
#define NCP_MAX 8192   // padded Ncols (HH*90 -> 8192)

typedef unsigned long long ull;

// ---------------- scratch (__device__ globals; no allocation) ----------------
__device__ float g_X0[N_NODES * F0];
__device__ float g_bufA[N_NODES * HH];
__device__ float g_bufB[N_NODES * HH];
__device__ float g_XT[HH * N_NODES];
__device__ float g_h[N_EDGES * HH];
__device__ float g_G[(size_t)N_NODES * NCP_MAX];   // 524 MB
__device__ float g_W2g[HH * NCP_MAX];
__device__ float g_xb[N_NODES * HH];
__device__ float g_agg[N_NODES * HH];
__device__ float g_pool[NGR * H2];
__device__ int   g_deg[N_NODES];
__device__ int   g_bucket[N_NODES * CAP];
__device__ int   g_ovf[N_EDGES];
__device__ int   g_ovfn;

// ---------------- f32x2 helpers ----------------
__device__ __forceinline__ ull pack2(float v) {
    ull r;
    asm("mov.b64 %0, {%1, %1};" : "=l"(r) : "f"(v));
    return r;
}
__device__ __forceinline__ void fma2(ull& d, ull a, ull b) {
    asm("fma.rn.f32x2 %0, %1, %2, %0;" : "+l"(d) : "l"(a), "l"(b));
}

// ---------------- small utility kernels ----------------
__global__ void zero_f(float* p, int n) {
    int i = blockIdx.x * blockDim.x + threadIdx.x;
    if (i < n) p[i] = 0.f;
}

__global__ void init_deg() {
    int i = blockIdx.x * blockDim.x + threadIdx.x;
    if (i < N_NODES) g_deg[i] = 0;
    if (i == 0) g_ovfn = 0;
}

__global__ void build_x0(const float* __restrict__ x, const float* __restrict__ pos) {
    int i = blockIdx.x * blockDim.x + threadIdx.x;
    if (i >= N_NODES * F0) return;
    int n = i / F0, c = i % F0;
    g_X0[i] = (c < 13) ? x[n * 13 + c] : pos[n * 3 + (c - 13)];
}

__global__ void bucket_build(const int* __restrict__ ei) {
    int e = blockIdx.x * blockDim.x + threadIdx.x;
    if (e >= N_EDGES) return;
    int s = ei[e];
    int slot = atomicAdd(&g_deg[s], 1);
    if (slot < CAP) g_bucket[s * CAP + slot] = e;
    else            g_ovf[atomicAdd(&g_ovfn, 1)] = e;
}

// XT[c][r] = X[r][c]
__global__ void transposeX(const float* __restrict__ X, float* __restrict__ XT, int in_c) {
    int idx = blockIdx.x * blockDim.x + threadIdx.x;
    if (idx >= in_c * N_NODES) return;
    int c = idx / N_NODES, r = idx - c * N_NODES;
    XT[idx] = X[r * in_c + c];
}

// h[e,:] = relu(edge_attr[e,:] @ w1 + b1)
__global__ void edge_mlp(const float* __restrict__ ea, const float* __restrict__ w1,
                         const float* __restrict__ b1, float* __restrict__ h) {
    int idx = blockIdx.x * blockDim.x + threadIdx.x;
    if (idx >= N_EDGES * HH) return;
    int e = idx / HH, o = idx % HH;
    float s = b1[o];
#pragma unroll
    for (int j = 0; j < EF; j++) s = fmaf(ea[e * EF + j], w1[j * HH + o], s);
    h[idx] = fmaxf(s, 0.f);
}

// W2g padded: W2g[i][col] = w2[k][i*out+o] for col=k*out+o < HH*out, else 0
__global__ void permW2(const float* __restrict__ w2, float* __restrict__ W2g,
                       int in_c, int out_c, int ncp) {
    int idx = blockIdx.x * blockDim.x + threadIdx.x;
    if (idx >= in_c * ncp) return;
    int i = idx / ncp, col = idx - i * ncp;
    float v = 0.f;
    if (col < HH * out_c) {
        int k = col / out_c, o = col - k * out_c;
        v = w2[(size_t)k * in_c * out_c + i * out_c + o];
    }
    W2g[idx] = v;
}

// ---------------- FFMA2 GEMM: C[M x ncp] = At^T[M x K] @ B[K x ncp] ----------------
// At: [K][M] (transposed A), B: [K][ncp], ncp % 128 == 0, M % 128 == 0
#define KC 32
__global__ __launch_bounds__(256, 2)
void gemm128(const float* __restrict__ At, const float* __restrict__ B,
             float* __restrict__ C, int M, int ncp, int K) {
    __shared__ float As[KC][128];
    __shared__ float Bs[KC][128];
    int tid = threadIdx.x;
    int rowBase = blockIdx.y * 128;
    int colBase = blockIdx.x * 128;
    int tx = tid & 15, ty = tid >> 4;
    int r0 = ty * 4, c0 = tx * 4;

    ull acc[8][4];
#pragma unroll
    for (int i = 0; i < 8; i++)
#pragma unroll
        for (int j = 0; j < 4; j++) acc[i][j] = 0ULL;

    for (int k0 = 0; k0 < K; k0 += KC) {
        int kc = min(KC, K - k0);
        for (int i = tid * 4; i < kc * 128; i += 1024) {
            int k = i >> 7, r = i & 127;
            *(float4*)&As[k][r] = *(const float4*)&At[(size_t)(k0 + k) * M + rowBase + r];
        }
        for (int i = tid * 4; i < kc * 128; i += 1024) {
            int k = i >> 7, c = i & 127;
            *(float4*)&Bs[k][c] = *(const float4*)&B[(size_t)(k0 + k) * ncp + colBase + c];
        }
        __syncthreads();

        for (int k = 0; k < kc; k++) {
            float4 a0 = *(const float4*)&As[k][r0];
            float4 a1 = *(const float4*)&As[k][64 + r0];
            ulonglong2 bb0 = *(const ulonglong2*)&Bs[k][c0];
            ulonglong2 bb1 = *(const ulonglong2*)&Bs[k][64 + c0];
            float av[8] = {a0.x, a0.y, a0.z, a0.w, a1.x, a1.y, a1.z, a1.w};
#pragma unroll
            for (int i = 0; i < 8; i++) {
                ull ap = pack2(av[i]);
                fma2(acc[i][0], ap, bb0.x);
                fma2(acc[i][1], ap, bb0.y);
                fma2(acc[i][2], ap, bb1.x);
                fma2(acc[i][3], ap, bb1.y);
            }
        }
        __syncthreads();
    }

    union U2 { ull u[2]; float4 f; };
#pragma unroll
    for (int i = 0; i < 8; i++) {
        int row = rowBase + ((i < 4) ? (r0 + i) : (64 + r0 + i - 4));
        U2 t0; t0.u[0] = acc[i][0]; t0.u[1] = acc[i][1];
        U2 t1; t1.u[0] = acc[i][2]; t1.u[1] = acc[i][3];
        *(float4*)&C[(size_t)row * ncp + colBase + c0]      = t0.f;
        *(float4*)&C[(size_t)row * ncp + colBase + 64 + c0] = t1.f;
    }
}

// xb[n,o] = sum_i Xin[n,i] * b2[i*out_c+o]
__global__ void xb_kernel(const float* __restrict__ Xin, const float* __restrict__ b2,
                          float* __restrict__ xb, int in_c, int out_c) {
    int n = blockIdx.x;
    __shared__ float xs[HH];
    for (int t = threadIdx.x; t < in_c; t += blockDim.x) xs[t] = Xin[n * in_c + t];
    __syncthreads();
    int o = threadIdx.x;
    if (o < out_c) {
        float acc = 0.f;
        for (int i = 0; i < in_c; i++) acc = fmaf(xs[i], __ldg(&b2[i * out_c + o]), acc);
        xb[n * out_c + o] = acc;
    }
}

// ---------------- per-src-node message + scatter to dst (loop-inverted) ----------------
__global__ void msg_kernel(const int* __restrict__ ei, int out_c, int strideG,
                           const float* __restrict__ G, const float* __restrict__ xb,
                           float* __restrict__ agg, const float* __restrict__ h) {
    int n = blockIdx.x;
    int d = g_deg[n];
    if (d == 0) return;
    if (d > CAP) d = CAP;
    __shared__ float hs[8][HH];
    __shared__ int dstS[8];
    const float* Grow = &G[(size_t)n * strideG];
    int o = threadIdx.x;
    float xbv = (o < out_c) ? xb[n * out_c + o] : 0.f;

    for (int base = 0; base < d; base += 8) {
        int m = min(8, d - base);
        for (int t = threadIdx.x; t < m * HH; t += blockDim.x) {
            int j = t / HH, k = t - j * HH;
            int e = g_bucket[n * CAP + base + j];
            hs[j][k] = h[e * HH + k];
        }
        if (threadIdx.x < m)
            dstS[threadIdx.x] = ei[N_EDGES + g_bucket[n * CAP + base + threadIdx.x]];
        __syncthreads();
        if (o < out_c) {
            float acc[8];
#pragma unroll
            for (int j = 0; j < 8; j++) acc[j] = 0.f;
            for (int k = 0; k < HH; k++) {
                float g = __ldg(&Grow[k * out_c + o]);
#pragma unroll
                for (int j = 0; j < 8; j++) acc[j] = fmaf(hs[j][k], g, acc[j]);
            }
            for (int j = 0; j < m; j++)
                atomicAdd(&agg[dstS[j] * out_c + o], acc[j] + xbv);
        }
        __syncthreads();
    }
}

// fallback for deg > CAP edges (rare)
__global__ void msg_ovf(const int* __restrict__ ei, int out_c, int strideG,
                        const float* __restrict__ G, const float* __restrict__ xb,
                        float* __restrict__ agg, const float* __restrict__ h) {
    __shared__ float hs[HH];
    for (int idx = blockIdx.x; idx < g_ovfn; idx += gridDim.x) {
        int e = g_ovf[idx];
        int n = ei[e];
        const float* Grow = &G[(size_t)n * strideG];
        for (int t = threadIdx.x; t < HH; t += blockDim.x) hs[t] = h[e * HH + t];
        __syncthreads();
        int o = threadIdx.x;
        if (o < out_c) {
            float acc = xb[n * out_c + o];
            for (int k = 0; k < HH; k++) acc = fmaf(hs[k], Grow[k * out_c + o], acc);
            atomicAdd(&agg[ei[N_EDGES + e] * out_c + o], acc);
        }
        __syncthreads();
    }
}

// out[n,:] = relu(agg[n,:] + Xin[n,:] @ root + bias)
__global__ void finalize_k(const float* __restrict__ Xin, float* __restrict__ Xout,
                           const float* __restrict__ root, const float* __restrict__ bias,
                           const float* __restrict__ agg, int in_c, int out_c) {
    int n = blockIdx.x;
    __shared__ float xs[HH];
    for (int t = threadIdx.x; t < in_c; t += blockDim.x) xs[t] = Xin[n * in_c + t];
    __syncthreads();
    int o = threadIdx.x;
    if (o < out_c) {
        float acc = agg[n * out_c + o] + bias[o];
        for (int i = 0; i < in_c; i++) acc = fmaf(xs[i], __ldg(&root[i * out_c + o]), acc);
        Xout[n * out_c + o] = fmaxf(acc, 0.f);
    }
}

__global__ void pool_add(const int* __restrict__ batch, const float* __restrict__ h3) {
    int idx = blockIdx.x * blockDim.x + threadIdx.x;
    if (idx >= N_NODES * H2) return;
    int n = idx / H2, o = idx % H2;
    atomicAdd(&g_pool[batch[n] * H2 + o], h3[idx]);
}

__global__ void head_k(const float* __restrict__ fc1w, const float* __restrict__ fc1b,
                       const float* __restrict__ outw, const float* __restrict__ outb,
                       float* __restrict__ out) {
    int g = blockIdx.x;
    __shared__ float ps[H2];
    __shared__ float fs[HH];
    for (int t = threadIdx.x; t < H2; t += blockDim.x) ps[t] = g_pool[g * H2 + t];
    __syncthreads();
    int o = threadIdx.x;
    if (o < HH) {
        float a = fc1b[o];
        for (int i = 0; i < H2; i++) a = fmaf(ps[i], fc1w[i * HH + o], a);
        fs[o] = fmaxf(a, 0.f);
    }
    __syncthreads();
    if (threadIdx.x == 0) {
        float s = outb[0];
        for (int q = 0; q < HH; q++) s = fmaf(fs[q], outw[q], s);
        out[g] = s;
    }
}

// ---------------- host orchestration ----------------
static void run_layer(const float* Xin, float* Xout, int in_c, int out_c,
                      const float* w1, const float* b1, const float* w2, const float* b2,
                      const float* root, const float* bias,
                      const float* ea, const int* ei,
                      float* XT, float* G, float* W2g, float* xb, float* agg, float* h) {
    int ncols = HH * out_c;
    int ncp = (ncols + 127) & ~127;   // 8192 or 4096

    edge_mlp<<<(N_EDGES * HH + 255) / 256, 256>>>(ea, w1, b1, h);
    transposeX<<<(in_c * N_NODES + 255) / 256, 256>>>(Xin, XT, in_c);
    permW2<<<(in_c * ncp + 255) / 256, 256>>>(w2, W2g, in_c, out_c, ncp);
    {
        dim3 gr(ncp / 128, N_NODES / 128);
        gemm128<<<gr, 256>>>(XT, W2g, G, N_NODES, ncp, in_c);
    }
    xb_kernel<<<N_NODES, 96>>>(Xin, b2, xb, in_c, out_c);
    zero_f<<<(N_NODES * out_c + 255) / 256, 256>>>(agg, N_NODES * out_c);
    int bs = ((out_c + 31) / 32) * 32;
    msg_kernel<<<N_NODES, bs>>>(ei, out_c, ncp, G, xb, agg, h);
    msg_ovf<<<128, bs>>>(ei, out_c, ncp, G, xb, agg, h);
    finalize_k<<<N_NODES, bs>>>(Xin, Xout, root, bias, agg, in_c, out_c);
}

extern "C" void kernel_launch(void* const* d_in, const int* in_sizes, int n_in,
                              void* d_out, int out_size) {
    const float* x    = (const float*)d_in[0];
    const float* pos  = (const float*)d_in[1];
    const float* ea   = (const float*)d_in[2];
    const int*   ei   = (const int*)  d_in[3];
    const int*   bat  = (const int*)  d_in[4];
    const float* c1w1 = (const float*)d_in[5];
    const float* c1b1 = (const float*)d_in[6];
    const float* c1w2 = (const float*)d_in[7];
    const float* c1b2 = (const float*)d_in[8];
    const float* c1r  = (const float*)d_in[9];
    const float* c1b  = (const float*)d_in[10];
    const float* c2w1 = (const float*)d_in[11];
    const float* c2b1 = (const float*)d_in[12];
    const float* c2w2 = (const float*)d_in[13];
    const float* c2b2 = (const float*)d_in[14];
    const float* c2r  = (const float*)d_in[15];
    const float* c2b  = (const float*)d_in[16];
    const float* c3w1 = (const float*)d_in[17];
    const float* c3b1 = (const float*)d_in[18];
    const float* c3w2 = (const float*)d_in[19];
    const float* c3b2 = (const float*)d_in[20];
    const float* c3r  = (const float*)d_in[21];
    const float* c3b  = (const float*)d_in[22];
    const float* f1w  = (const float*)d_in[23];
    const float* f1b  = (const float*)d_in[24];
    const float* ow   = (const float*)d_in[25];
    const float* ob   = (const float*)d_in[26];
    float* out = (float*)d_out;

    void *pX0, *pA, *pB, *pXT, *pG, *pW2g, *pxb, *pagg, *ph, *ppool;
    cudaGetSymbolAddress(&pX0, g_X0);
    cudaGetSymbolAddress(&pA, g_bufA);
    cudaGetSymbolAddress(&pB, g_bufB);
    cudaGetSymbolAddress(&pXT, g_XT);
    cudaGetSymbolAddress(&pG, g_G);
    cudaGetSymbolAddress(&pW2g, g_W2g);
    cudaGetSymbolAddress(&pxb, g_xb);
    cudaGetSymbolAddress(&pagg, g_agg);
    cudaGetSymbolAddress(&ph, g_h);
    cudaGetSymbolAddress(&ppool, g_pool);
    float* X0  = (float*)pX0;
    float* bufA= (float*)pA;
    float* bufB= (float*)pB;
    float* XT  = (float*)pXT;
    float* G   = (float*)pG;
    float* W2g = (float*)pW2g;
    float* xb  = (float*)pxb;
    float* agg = (float*)pagg;
    float* h   = (float*)ph;
    float* pool= (float*)ppool;

    build_x0<<<(N_NODES * F0 + 255) / 256, 256>>>(x, pos);
    init_deg<<<(N_NODES + 255) / 256, 256>>>();
    bucket_build<<<(N_EDGES + 255) / 256, 256>>>(ei);

    // layer 1: 16 -> 90
    run_layer(X0, bufA, F0, HH, c1w1, c1b1, c1w2, c1b2, c1r, c1b, ea, ei, XT, G, W2g, xb, agg, h);
    // layer 2: 90 -> 90
    run_layer(bufA, bufB, HH, HH, c2w1, c2b1, c2w2, c2b2, c2r, c2b, ea, ei, XT, G, W2g, xb, agg, h);
    // layer 3: 90 -> 45
    run_layer(bufB, bufA, HH, H2, c3w1, c3b1, c3w2, c3b2, c3r, c3b, ea, ei, XT, G, W2g, xb, agg, h);

    zero_f<<<(NGR * H2 + 255) / 256, 256>>>(pool, NGR * H2);
    pool_add<<<(N_NODES * H2 + 255) / 256, 256>>>(bat, bufA);
    head_k<<<NGR, 96>>>(f1w, f1b, ow, ob, out);
}

// round 4
// speedup vs baseline: 1.6528x; 1.1115x over previous
#include <cuda_runtime.h>
#include <math.h>
#include <stdint.h>

#define N_NODES 16000
#define N_EDGES 64000
#define HH 90
#define F0 16
#define EF 8
#define NGR 512
#define H2 45
#define CAP 64
#define NCP_MAX 8192
#define KP_MAX 96
#define CK 32
#define LDC 36

// ---------------- scratch (__device__ globals; no allocation) ----------------
__device__ float g_X0[N_NODES * F0];
__device__ float g_bufA[N_NODES * HH];
__device__ float g_bufB[N_NODES * HH];
__device__ float g_h[N_EDGES * HH];
__device__ float g_G[(size_t)N_NODES * NCP_MAX];     // 524 MB
__device__ float g_BT[NCP_MAX * KP_MAX];             // B transposed [ncp][kp], zero-padded
__device__ float g_xb[N_NODES * HH];
__device__ float g_agg[N_NODES * HH];
__device__ float g_pool[NGR * H2];
__device__ int   g_deg[N_NODES];
__device__ int   g_bucket[N_NODES * CAP];
__device__ int   g_ovf[N_EDGES];
__device__ int   g_ovfn;

// ---------------- tf32 mma.sync GEMM: C[M x ncp] = A[M x in_c] @ BT^T ----------------
// A row-major [M][in_c]; BT [ncp][kp] zero-padded; C [M][ncp]. M%128==0, ncp%128==0, kp%32==0.
__global__ __launch_bounds__(256, 2)
void mma_gemm(const float* __restrict__ A, const float* __restrict__ BT,
              float* __restrict__ C, int in_c, int ncp, int kp) {
    __shared__ uint32_t As[128 * LDC];   // [row][k-chunk], tf32 bits
    __shared__ uint32_t Bs[128 * LDC];   // [col][k-chunk], tf32 bits

    const int tid = threadIdx.x;
    const int lane = tid & 31, wid = tid >> 5;
    const int rowBase = blockIdx.y * 128, colBase = blockIdx.x * 128;
    const int warpRow = (wid & 3) * 32;   // 4 row groups of 32
    const int warpCol = (wid >> 2) * 64;  // 2 col groups of 64
    const int qr = lane >> 2, qk = lane & 3;

    float acc[2][8][4];
#pragma unroll
    for (int mt = 0; mt < 2; mt++)
#pragma unroll
        for (int nt = 0; nt < 8; nt++)
#pragma unroll
            for (int j = 0; j < 4; j++) acc[mt][nt][j] = 0.f;

    for (int kc = 0; kc < kp; kc += CK) {
        // fill A chunk (coalesced global reads, conflict-free smem writes)
        for (int idx = tid; idx < 128 * CK; idx += 256) {
            int row = idx >> 5, k = idx & 31;
            int gk = kc + k;
            float v = (gk < in_c) ? A[(size_t)(rowBase + row) * in_c + gk] : 0.f;
            uint32_t t;
            asm("cvt.rna.tf32.f32 %0, %1;" : "=r"(t) : "f"(v));
            As[row * LDC + k] = t;
        }
        // fill B chunk from BT (already zero-padded to kp)
        for (int idx = tid; idx < 128 * CK; idx += 256) {
            int col = idx >> 5, k = idx & 31;
            float v = BT[(size_t)(colBase + col) * kp + kc + k];
            uint32_t t;
            asm("cvt.rna.tf32.f32 %0, %1;" : "=r"(t) : "f"(v));
            Bs[col * LDC + k] = t;
        }
        __syncthreads();

#pragma unroll
        for (int ks = 0; ks < CK; ks += 8) {
            uint32_t a[2][4];
#pragma unroll
            for (int mt = 0; mt < 2; mt++) {
                int r = warpRow + mt * 16 + qr;
                a[mt][0] = As[r * LDC + ks + qk];
                a[mt][1] = As[(r + 8) * LDC + ks + qk];
                a[mt][2] = As[r * LDC + ks + qk + 4];
                a[mt][3] = As[(r + 8) * LDC + ks + qk + 4];
            }
#pragma unroll
            for (int nt = 0; nt < 8; nt++) {
                int c = warpCol + nt * 8 + qr;
                uint32_t b0 = Bs[c * LDC + ks + qk];
                uint32_t b1 = Bs[c * LDC + ks + qk + 4];
#pragma unroll
                for (int mt = 0; mt < 2; mt++) {
                    asm volatile(
                        "mma.sync.aligned.m16n8k8.row.col.f32.tf32.tf32.f32 "
                        "{%0,%1,%2,%3}, {%4,%5,%6,%7}, {%8,%9}, {%0,%1,%2,%3};"
                        : "+f"(acc[mt][nt][0]), "+f"(acc[mt][nt][1]),
                          "+f"(acc[mt][nt][2]), "+f"(acc[mt][nt][3])
                        : "r"(a[mt][0]), "r"(a[mt][1]), "r"(a[mt][2]), "r"(a[mt][3]),
                          "r"(b0), "r"(b1));
                }
            }
        }
        __syncthreads();
    }

    // epilogue: direct global stores (float2 per fragment half)
#pragma unroll
    for (int mt = 0; mt < 2; mt++) {
        int r = rowBase + warpRow + mt * 16 + qr;
#pragma unroll
        for (int nt = 0; nt < 8; nt++) {
            int c = colBase + warpCol + nt * 8 + qk * 2;
            *(float2*)&C[(size_t)r * ncp + c] = make_float2(acc[mt][nt][0], acc[mt][nt][1]);
            *(float2*)&C[(size_t)(r + 8) * ncp + c] = make_float2(acc[mt][nt][2], acc[mt][nt][3]);
        }
    }
}

// ---------------- small utility kernels ----------------
__global__ void zero_f(float* p, int n) {
    int i = blockIdx.x * blockDim.x + threadIdx.x;
    if (i < n) p[i] = 0.f;
}

__global__ void init_deg() {
    int i = blockIdx.x * blockDim.x + threadIdx.x;
    if (i < N_NODES) g_deg[i] = 0;
    if (i == 0) g_ovfn = 0;
}

__global__ void build_x0(const float* __restrict__ x, const float* __restrict__ pos) {
    int i = blockIdx.x * blockDim.x + threadIdx.x;
    if (i >= N_NODES * F0) return;
    int n = i / F0, c = i % F0;
    g_X0[i] = (c < 13) ? x[n * 13 + c] : pos[n * 3 + (c - 13)];
}

__global__ void bucket_build(const int* __restrict__ ei) {
    int e = blockIdx.x * blockDim.x + threadIdx.x;
    if (e >= N_EDGES) return;
    int s = ei[e];
    int slot = atomicAdd(&g_deg[s], 1);
    if (slot < CAP) g_bucket[s * CAP + slot] = e;
    else            g_ovf[atomicAdd(&g_ovfn, 1)] = e;
}

// h[e,:] = relu(edge_attr[e,:] @ w1 + b1)
__global__ void edge_mlp(const float* __restrict__ ea, const float* __restrict__ w1,
                         const float* __restrict__ b1, float* __restrict__ h) {
    int idx = blockIdx.x * blockDim.x + threadIdx.x;
    if (idx >= N_EDGES * HH) return;
    int e = idx / HH, o = idx % HH;
    float s = b1[o];
#pragma unroll
    for (int j = 0; j < EF; j++) s = fmaf(ea[e * EF + j], w1[j * HH + o], s);
    h[idx] = fmaxf(s, 0.f);
}

// BT[col][k] = w2[kk][k*out+o] where col = kk*out_c + o   (zero-padded)
__global__ void buildBT(const float* __restrict__ w2, float* __restrict__ BT,
                        int in_c, int out_c, int ncp, int kp) {
    int idx = blockIdx.x * blockDim.x + threadIdx.x;
    if (idx >= ncp * kp) return;
    int col = idx / kp, k = idx - col * kp;
    float v = 0.f;
    if (col < HH * out_c && k < in_c) {
        int kk = col / out_c, o = col - kk * out_c;
        v = w2[((size_t)kk * in_c + k) * out_c + o];
    }
    BT[idx] = v;
}

// xb[n,o] = sum_i Xin[n,i] * b2[i*out_c+o]
__global__ void xb_kernel(const float* __restrict__ Xin, const float* __restrict__ b2,
                          float* __restrict__ xb, int in_c, int out_c) {
    int n = blockIdx.x;
    __shared__ float xs[HH];
    for (int t = threadIdx.x; t < in_c; t += blockDim.x) xs[t] = Xin[n * in_c + t];
    __syncthreads();
    int o = threadIdx.x;
    if (o < out_c) {
        float acc = 0.f;
        for (int i = 0; i < in_c; i++) acc = fmaf(xs[i], __ldg(&b2[i * out_c + o]), acc);
        xb[n * out_c + o] = acc;
    }
}

// ---------------- per-src-node message + scatter to dst (loop-inverted) ----------------
__global__ void msg_kernel(const int* __restrict__ ei, int out_c, int strideG,
                           const float* __restrict__ G, const float* __restrict__ xb,
                           float* __restrict__ agg, const float* __restrict__ h) {
    int n = blockIdx.x;
    int d = g_deg[n];
    if (d == 0) return;
    if (d > CAP) d = CAP;
    __shared__ float hs[8][HH];
    __shared__ int dstS[8];
    const float* Grow = &G[(size_t)n * strideG];
    int o = threadIdx.x;
    float xbv = (o < out_c) ? xb[n * out_c + o] : 0.f;

    for (int base = 0; base < d; base += 8) {
        int m = min(8, d - base);
        for (int t = threadIdx.x; t < m * HH; t += blockDim.x) {
            int j = t / HH, k = t - j * HH;
            int e = g_bucket[n * CAP + base + j];
            hs[j][k] = h[e * HH + k];
        }
        if (threadIdx.x < m)
            dstS[threadIdx.x] = ei[N_EDGES + g_bucket[n * CAP + base + threadIdx.x]];
        __syncthreads();
        if (o < out_c) {
            float acc[8];
#pragma unroll
            for (int j = 0; j < 8; j++) acc[j] = 0.f;
            for (int k = 0; k < HH; k++) {
                float g = __ldg(&Grow[k * out_c + o]);
#pragma unroll
                for (int j = 0; j < 8; j++) acc[j] = fmaf(hs[j][k], g, acc[j]);
            }
            for (int j = 0; j < m; j++)
                atomicAdd(&agg[dstS[j] * out_c + o], acc[j] + xbv);
        }
        __syncthreads();
    }
}

// fallback for deg > CAP edges (rare)
__global__ void msg_ovf(const int* __restrict__ ei, int out_c, int strideG,
                        const float* __restrict__ G, const float* __restrict__ xb,
                        float* __restrict__ agg, const float* __restrict__ h) {
    __shared__ float hs[HH];
    for (int idx = blockIdx.x; idx < g_ovfn; idx += gridDim.x) {
        int e = g_ovf[idx];
        int n = ei[e];
        const float* Grow = &G[(size_t)n * strideG];
        for (int t = threadIdx.x; t < HH; t += blockDim.x) hs[t] = h[e * HH + t];
        __syncthreads();
        int o = threadIdx.x;
        if (o < out_c) {
            float acc = xb[n * out_c + o];
            for (int k = 0; k < HH; k++) acc = fmaf(hs[k], Grow[k * out_c + o], acc);
            atomicAdd(&agg[ei[N_EDGES + e] * out_c + o], acc);
        }
        __syncthreads();
    }
}

// out[n,:] = relu(agg[n,:] + Xin[n,:] @ root + bias)
__global__ void finalize_k(const float* __restrict__ Xin, float* __restrict__ Xout,
                           const float* __restrict__ root, const float* __restrict__ bias,
                           const float* __restrict__ agg, int in_c, int out_c) {
    int n = blockIdx.x;
    __shared__ float xs[HH];
    for (int t = threadIdx.x; t < in_c; t += blockDim.x) xs[t] = Xin[n * in_c + t];
    __syncthreads();
    int o = threadIdx.x;
    if (o < out_c) {
        float acc = agg[n * out_c + o] + bias[o];
        for (int i = 0; i < in_c; i++) acc = fmaf(xs[i], __ldg(&root[i * out_c + o]), acc);
        Xout[n * out_c + o] = fmaxf(acc, 0.f);
    }
}

__global__ void pool_add(const int* __restrict__ batch, const float* __restrict__ h3) {
    int idx = blockIdx.x * blockDim.x + threadIdx.x;
    if (idx >= N_NODES * H2) return;
    int n = idx / H2, o = idx % H2;
    atomicAdd(&g_pool[batch[n] * H2 + o], h3[idx]);
}

__global__ void head_k(const float* __restrict__ fc1w, const float* __restrict__ fc1b,
                       const float* __restrict__ outw, const float* __restrict__ outb,
                       float* __restrict__ out) {
    int g = blockIdx.x;
    __shared__ float ps[H2];
    __shared__ float fs[HH];
    for (int t = threadIdx.x; t < H2; t += blockDim.x) ps[t] = g_pool[g * H2 + t];
    __syncthreads();
    int o = threadIdx.x;
    if (o < HH) {
        float a = fc1b[o];
        for (int i = 0; i < H2; i++) a = fmaf(ps[i], fc1w[i * HH + o], a);
        fs[o] = fmaxf(a, 0.f);
    }
    __syncthreads();
    if (threadIdx.x == 0) {
        float s = outb[0];
        for (int q = 0; q < HH; q++) s = fmaf(fs[q], outw[q], s);
        out[g] = s;
    }
}

// ---------------- host orchestration ----------------
static void run_layer(const float* Xin, float* Xout, int in_c, int out_c,
                      const float* w1, const float* b1, const float* w2, const float* b2,
                      const float* root, const float* bias,
                      const float* ea, const int* ei,
                      float* G, float* BT, float* xb, float* agg, float* h) {
    int ncols = HH * out_c;
    int ncp = (ncols + 127) & ~127;             // 8192 / 4096
    int kp = ((in_c + 31) & ~31);               // 32 / 96

    edge_mlp<<<(N_EDGES * HH + 255) / 256, 256>>>(ea, w1, b1, h);
    buildBT<<<(ncp * kp + 255) / 256, 256>>>(w2, BT, in_c, out_c, ncp, kp);
    {
        dim3 gr(ncp / 128, N_NODES / 128);
        mma_gemm<<<gr, 256>>>(Xin, BT, G, in_c, ncp, kp);
    }
    xb_kernel<<<N_NODES, 96>>>(Xin, b2, xb, in_c, out_c);
    zero_f<<<(N_NODES * out_c + 255) / 256, 256>>>(agg, N_NODES * out_c);
    int bs = ((out_c + 31) / 32) * 32;
    msg_kernel<<<N_NODES, bs>>>(ei, out_c, ncp, G, xb, agg, h);
    msg_ovf<<<128, bs>>>(ei, out_c, ncp, G, xb, agg, h);
    finalize_k<<<N_NODES, bs>>>(Xin, Xout, root, bias, agg, in_c, out_c);
}

extern "C" void kernel_launch(void* const* d_in, const int* in_sizes, int n_in,
                              void* d_out, int out_size) {
    const float* x    = (const float*)d_in[0];
    const float* pos  = (const float*)d_in[1];
    const float* ea   = (const float*)d_in[2];
    const int*   ei   = (const int*)  d_in[3];
    const int*   bat  = (const int*)  d_in[4];
    const float* c1w1 = (const float*)d_in[5];
    const float* c1b1 = (const float*)d_in[6];
    const float* c1w2 = (const float*)d_in[7];
    const float* c1b2 = (const float*)d_in[8];
    const float* c1r  = (const float*)d_in[9];
    const float* c1b  = (const float*)d_in[10];
    const float* c2w1 = (const float*)d_in[11];
    const float* c2b1 = (const float*)d_in[12];
    const float* c2w2 = (const float*)d_in[13];
    const float* c2b2 = (const float*)d_in[14];
    const float* c2r  = (const float*)d_in[15];
    const float* c2b  = (const float*)d_in[16];
    const float* c3w1 = (const float*)d_in[17];
    const float* c3b1 = (const float*)d_in[18];
    const float* c3w2 = (const float*)d_in[19];
    const float* c3b2 = (const float*)d_in[20];
    const float* c3r  = (const float*)d_in[21];
    const float* c3b  = (const float*)d_in[22];
    const float* f1w  = (const float*)d_in[23];
    const float* f1b  = (const float*)d_in[24];
    const float* ow   = (const float*)d_in[25];
    const float* ob   = (const float*)d_in[26];
    float* out = (float*)d_out;

    void *pX0, *pA, *pB, *pG, *pBT, *pxb, *pagg, *ph, *ppool;
    cudaGetSymbolAddress(&pX0, g_X0);
    cudaGetSymbolAddress(&pA, g_bufA);
    cudaGetSymbolAddress(&pB, g_bufB);
    cudaGetSymbolAddress(&pG, g_G);
    cudaGetSymbolAddress(&pBT, g_BT);
    cudaGetSymbolAddress(&pxb, g_xb);
    cudaGetSymbolAddress(&pagg, g_agg);
    cudaGetSymbolAddress(&ph, g_h);
    cudaGetSymbolAddress(&ppool, g_pool);
    float* X0  = (float*)pX0;
    float* bufA= (float*)pA;
    float* bufB= (float*)pB;
    float* G   = (float*)pG;
    float* BT  = (float*)pBT;
    float* xb  = (float*)pxb;
    float* agg = (float*)pagg;
    float* h   = (float*)ph;
    float* pool= (float*)ppool;

    build_x0<<<(N_NODES * F0 + 255) / 256, 256>>>(x, pos);
    init_deg<<<(N_NODES + 255) / 256, 256>>>();
    bucket_build<<<(N_EDGES + 255) / 256, 256>>>(ei);

    // layer 1: 16 -> 90
    run_layer(X0, bufA, F0, HH, c1w1, c1b1, c1w2, c1b2, c1r, c1b, ea, ei, G, BT, xb, agg, h);
    // layer 2: 90 -> 90
    run_layer(bufA, bufB, HH, HH, c2w1, c2b1, c2w2, c2b2, c2r, c2b, ea, ei, G, BT, xb, agg, h);
    // layer 3: 90 -> 45
    run_layer(bufB, bufA, HH, H2, c3w1, c3b1, c3w2, c3b2, c3r, c3b, ea, ei, G, BT, xb, agg, h);

    zero_f<<<(NGR * H2 + 255) / 256, 256>>>(pool, NGR * H2);
    pool_add<<<(N_NODES * H2 + 255) / 256, 256>>>(bat, bufA);
    head_k<<<NGR, 96>>>(f1w, f1b, ow, ob, out);
}

// round 6
// speedup vs baseline: 1.7597x; 1.0647x over previous
#include <cuda_runtime.h>
#include <cuda_fp16.h>
#include <math.h>
#include <stdint.h>

#define N_NODES 16000
#define N_EDGES 64000
#define HH 90
#define F0 16
#define EF 8
#define NGR 512
#define H2 45
#define CAP 64
#define NCP_MAX 8192
#define KP_MAX 96
#define CK 32
#define LDC 36

// ---------------- scratch (__device__ globals; no allocation) ----------------
__device__ float g_X0[N_NODES * F0];
__device__ float g_bufA[N_NODES * HH];
__device__ float g_bufB[N_NODES * HH];
__device__ float g_h[N_EDGES * HH];
__device__ __half g_G[(size_t)N_NODES * NCP_MAX];          // 262 MB (fp16)
__device__ float g_BT[NCP_MAX * KP_MAX];                   // B transposed [ncp][kp], zero-padded
__device__ float g_xb[N_NODES * HH];
__device__ float g_agg[N_NODES * HH];
__device__ float g_pool[NGR * H2];
__device__ int   g_deg[N_NODES];
__device__ int   g_bucket[N_NODES * CAP];
__device__ int   g_ovf[N_EDGES];
__device__ int   g_ovfn;

// ---------------- tf32 mma.sync GEMM: G[M x ncp](fp16) = A[M x in_c] @ BT^T ----------------
// A row-major [M][in_c]; BT [ncp][kp] zero-padded; M%128==0, ncp%128==0, kp%32==0.
__global__ __launch_bounds__(256, 2)
void mma_gemm(const float* __restrict__ A, const float* __restrict__ BT,
              __half* __restrict__ C, int in_c, int ncp, int kp) {
    __shared__ uint32_t As[128 * LDC];   // [row][k-chunk], tf32 bits
    __shared__ uint32_t Bs[128 * LDC];   // [col][k-chunk], tf32 bits

    const int tid = threadIdx.x;
    const int lane = tid & 31, wid = tid >> 5;
    const int rowBase = blockIdx.y * 128, colBase = blockIdx.x * 128;
    const int warpRow = (wid & 3) * 32;   // 4 row groups of 32
    const int warpCol = (wid >> 2) * 64;  // 2 col groups of 64
    const int qr = lane >> 2, qk = lane & 3;

    float acc[2][8][4];
#pragma unroll
    for (int mt = 0; mt < 2; mt++)
#pragma unroll
        for (int nt = 0; nt < 8; nt++)
#pragma unroll
            for (int j = 0; j < 4; j++) acc[mt][nt][j] = 0.f;

    for (int kc = 0; kc < kp; kc += CK) {
        for (int idx = tid; idx < 128 * CK; idx += 256) {
            int row = idx >> 5, k = idx & 31;
            int gk = kc + k;
            float v = (gk < in_c) ? A[(size_t)(rowBase + row) * in_c + gk] : 0.f;
            uint32_t t;
            asm("cvt.rna.tf32.f32 %0, %1;" : "=r"(t) : "f"(v));
            As[row * LDC + k] = t;
        }
        for (int idx = tid; idx < 128 * CK; idx += 256) {
            int col = idx >> 5, k = idx & 31;
            float v = BT[(size_t)(colBase + col) * kp + kc + k];
            uint32_t t;
            asm("cvt.rna.tf32.f32 %0, %1;" : "=r"(t) : "f"(v));
            Bs[col * LDC + k] = t;
        }
        __syncthreads();

#pragma unroll
        for (int ks = 0; ks < CK; ks += 8) {
            uint32_t a[2][4];
#pragma unroll
            for (int mt = 0; mt < 2; mt++) {
                int r = warpRow + mt * 16 + qr;
                a[mt][0] = As[r * LDC + ks + qk];
                a[mt][1] = As[(r + 8) * LDC + ks + qk];
                a[mt][2] = As[r * LDC + ks + qk + 4];
                a[mt][3] = As[(r + 8) * LDC + ks + qk + 4];
            }
#pragma unroll
            for (int nt = 0; nt < 8; nt++) {
                int c = warpCol + nt * 8 + qr;
                uint32_t b0 = Bs[c * LDC + ks + qk];
                uint32_t b1 = Bs[c * LDC + ks + qk + 4];
#pragma unroll
                for (int mt = 0; mt < 2; mt++) {
                    asm volatile(
                        "mma.sync.aligned.m16n8k8.row.col.f32.tf32.tf32.f32 "
                        "{%0,%1,%2,%3}, {%4,%5,%6,%7}, {%8,%9}, {%0,%1,%2,%3};"
                        : "+f"(acc[mt][nt][0]), "+f"(acc[mt][nt][1]),
                          "+f"(acc[mt][nt][2]), "+f"(acc[mt][nt][3])
                        : "r"(a[mt][0]), "r"(a[mt][1]), "r"(a[mt][2]), "r"(a[mt][3]),
                          "r"(b0), "r"(b1));
                }
            }
        }
        __syncthreads();
    }

    // epilogue: half2 stores (halved traffic)
#pragma unroll
    for (int mt = 0; mt < 2; mt++) {
        int r = rowBase + warpRow + mt * 16 + qr;
#pragma unroll
        for (int nt = 0; nt < 8; nt++) {
            int c = colBase + warpCol + nt * 8 + qk * 2;
            __half2 v0 = __floats2half2_rn(acc[mt][nt][0], acc[mt][nt][1]);
            __half2 v1 = __floats2half2_rn(acc[mt][nt][2], acc[mt][nt][3]);
            *(__half2*)&C[(size_t)r * ncp + c] = v0;
            *(__half2*)&C[(size_t)(r + 8) * ncp + c] = v1;
        }
    }
}

// ---------------- small utility kernels ----------------
__global__ void zero_f(float* p, int n) {
    int i = blockIdx.x * blockDim.x + threadIdx.x;
    if (i < n) p[i] = 0.f;
}

__global__ void init_deg() {
    int i = blockIdx.x * blockDim.x + threadIdx.x;
    if (i < N_NODES) g_deg[i] = 0;
    if (i == 0) g_ovfn = 0;
}

__global__ void build_x0(const float* __restrict__ x, const float* __restrict__ pos) {
    int i = blockIdx.x * blockDim.x + threadIdx.x;
    if (i >= N_NODES * F0) return;
    int n = i / F0, c = i % F0;
    g_X0[i] = (c < 13) ? x[n * 13 + c] : pos[n * 3 + (c - 13)];
}

__global__ void bucket_build(const int* __restrict__ ei) {
    int e = blockIdx.x * blockDim.x + threadIdx.x;
    if (e >= N_EDGES) return;
    int s = ei[e];
    int slot = atomicAdd(&g_deg[s], 1);
    if (slot < CAP) g_bucket[s * CAP + slot] = e;
    else            g_ovf[atomicAdd(&g_ovfn, 1)] = e;
}

// h[e,:] = relu(edge_attr[e,:] @ w1 + b1)
__global__ void edge_mlp(const float* __restrict__ ea, const float* __restrict__ w1,
                         const float* __restrict__ b1, float* __restrict__ h) {
    int idx = blockIdx.x * blockDim.x + threadIdx.x;
    if (idx >= N_EDGES * HH) return;
    int e = idx / HH, o = idx % HH;
    float s = b1[o];
#pragma unroll
    for (int j = 0; j < EF; j++) s = fmaf(ea[e * EF + j], w1[j * HH + o], s);
    h[idx] = fmaxf(s, 0.f);
}

// BT[col][k] = w2[kk][k*out+o] where col = kk*out_c + o   (zero-padded)
__global__ void buildBT(const float* __restrict__ w2, float* __restrict__ BT,
                        int in_c, int out_c, int ncp, int kp) {
    int idx = blockIdx.x * blockDim.x + threadIdx.x;
    if (idx >= ncp * kp) return;
    int col = idx / kp, k = idx - col * kp;
    float v = 0.f;
    if (col < HH * out_c && k < in_c) {
        int kk = col / out_c, o = col - kk * out_c;
        v = w2[((size_t)kk * in_c + k) * out_c + o];
    }
    BT[idx] = v;
}

// xb[n,o] = sum_i Xin[n,i] * b2[i*out_c+o]
__global__ void xb_kernel(const float* __restrict__ Xin, const float* __restrict__ b2,
                          float* __restrict__ xb, int in_c, int out_c) {
    int n = blockIdx.x;
    __shared__ float xs[HH];
    for (int t = threadIdx.x; t < in_c; t += blockDim.x) xs[t] = Xin[n * in_c + t];
    __syncthreads();
    int o = threadIdx.x;
    if (o < out_c) {
        float acc = 0.f;
        for (int i = 0; i < in_c; i++) acc = fmaf(xs[i], __ldg(&b2[i * out_c + o]), acc);
        xb[n * out_c + o] = acc;
    }
}

// ---------------- per-src-node message + scatter to dst (loop-inverted, fp16 G) ----------------
__global__ void msg_kernel(const int* __restrict__ ei, int out_c, int strideG,
                           const __half* __restrict__ G, const float* __restrict__ xb,
                           float* __restrict__ agg, const float* __restrict__ h) {
    int n = blockIdx.x;
    int d = g_deg[n];
    if (d == 0) return;
    if (d > CAP) d = CAP;
    __shared__ float hs[8][HH];
    __shared__ int dstS[8];
    const __half* Grow = &G[(size_t)n * strideG];
    int o = threadIdx.x;
    float xbv = (o < out_c) ? xb[n * out_c + o] : 0.f;

    for (int base = 0; base < d; base += 8) {
        int m = min(8, d - base);
        for (int t = threadIdx.x; t < m * HH; t += blockDim.x) {
            int j = t / HH, k = t - j * HH;
            int e = g_bucket[n * CAP + base + j];
            hs[j][k] = h[e * HH + k];
        }
        if (threadIdx.x < m)
            dstS[threadIdx.x] = ei[N_EDGES + g_bucket[n * CAP + base + threadIdx.x]];
        __syncthreads();
        if (o < out_c) {
            float acc[8];
#pragma unroll
            for (int j = 0; j < 8; j++) acc[j] = 0.f;
            for (int k = 0; k < HH; k++) {
                float g = __half2float(Grow[k * out_c + o]);
#pragma unroll
                for (int j = 0; j < 8; j++) acc[j] = fmaf(hs[j][k], g, acc[j]);
            }
            for (int j = 0; j < m; j++)
                atomicAdd(&agg[dstS[j] * out_c + o], acc[j] + xbv);
        }
        __syncthreads();
    }
}

// fallback for deg > CAP edges (rare)
__global__ void msg_ovf(const int* __restrict__ ei, int out_c, int strideG,
                        const __half* __restrict__ G, const float* __restrict__ xb,
                        float* __restrict__ agg, const float* __restrict__ h) {
    __shared__ float hs[HH];
    for (int idx = blockIdx.x; idx < g_ovfn; idx += gridDim.x) {
        int e = g_ovf[idx];
        int n = ei[e];
        const __half* Grow = &G[(size_t)n * strideG];
        for (int t = threadIdx.x; t < HH; t += blockDim.x) hs[t] = h[e * HH + t];
        __syncthreads();
        int o = threadIdx.x;
        if (o < out_c) {
            float acc = xb[n * out_c + o];
            for (int k = 0; k < HH; k++) acc = fmaf(hs[k], __half2float(Grow[k * out_c + o]), acc);
            atomicAdd(&agg[ei[N_EDGES + e] * out_c + o], acc);
        }
        __syncthreads();
    }
}

// out[n,:] = relu(agg[n,:] + Xin[n,:] @ root + bias)
__global__ void finalize_k(const float* __restrict__ Xin, float* __restrict__ Xout,
                           const float* __restrict__ root, const float* __restrict__ bias,
                           const float* __restrict__ agg, int in_c, int out_c) {
    int n = blockIdx.x;
    __shared__ float xs[HH];
    for (int t = threadIdx.x; t < in_c; t += blockDim.x) xs[t] = Xin[n * in_c + t];
    __syncthreads();
    int o = threadIdx.x;
    if (o < out_c) {
        float acc = agg[n * out_c + o] + bias[o];
        for (int i = 0; i < in_c; i++) acc = fmaf(xs[i], __ldg(&root[i * out_c + o]), acc);
        Xout[n * out_c + o] = fmaxf(acc, 0.f);
    }
}

__global__ void pool_add(const int* __restrict__ batch, const float* __restrict__ h3) {
    int idx = blockIdx.x * blockDim.x + threadIdx.x;
    if (idx >= N_NODES * H2) return;
    int n = idx / H2, o = idx % H2;
    atomicAdd(&g_pool[batch[n] * H2 + o], h3[idx]);
}

__global__ void head_k(const float* __restrict__ fc1w, const float* __restrict__ fc1b,
                       const float* __restrict__ outw, const float* __restrict__ outb,
                       float* __restrict__ out) {
    int g = blockIdx.x;
    __shared__ float ps[H2];
    __shared__ float fs[HH];
    for (int t = threadIdx.x; t < H2; t += blockDim.x) ps[t] = g_pool[g * H2 + t];
    __syncthreads();
    int o = threadIdx.x;
    if (o < HH) {
        float a = fc1b[o];
        for (int i = 0; i < H2; i++) a = fmaf(ps[i], fc1w[i * HH + o], a);
        fs[o] = fmaxf(a, 0.f);
    }
    __syncthreads();
    if (threadIdx.x == 0) {
        float s = outb[0];
        for (int q = 0; q < HH; q++) s = fmaf(fs[q], outw[q], s);
        out[g] = s;
    }
}

// ---------------- host orchestration ----------------
static void run_layer(const float* Xin, float* Xout, int in_c, int out_c,
                      const float* w1, const float* b1, const float* w2, const float* b2,
                      const float* root, const float* bias,
                      const float* ea, const int* ei,
                      __half* G, float* BT, float* xb, float* agg, float* h) {
    int ncols = HH * out_c;
    int ncp = (ncols + 127) & ~127;             // 8192 / 4096
    int kp = ((in_c + 31) & ~31);               // 32 / 96

    edge_mlp<<<(N_EDGES * HH + 255) / 256, 256>>>(ea, w1, b1, h);
    buildBT<<<(ncp * kp + 255) / 256, 256>>>(w2, BT, in_c, out_c, ncp, kp);
    {
        dim3 gr(ncp / 128, N_NODES / 128);
        mma_gemm<<<gr, 256>>>(Xin, BT, G, in_c, ncp, kp);
    }
    xb_kernel<<<N_NODES, 96>>>(Xin, b2, xb, in_c, out_c);
    zero_f<<<(N_NODES * out_c + 255) / 256, 256>>>(agg, N_NODES * out_c);
    int bs = ((out_c + 31) / 32) * 32;
    msg_kernel<<<N_NODES, bs>>>(ei, out_c, ncp, G, xb, agg, h);
    msg_ovf<<<128, bs>>>(ei, out_c, ncp, G, xb, agg, h);
    finalize_k<<<N_NODES, bs>>>(Xin, Xout, root, bias, agg, in_c, out_c);
}

extern "C" void kernel_launch(void* const* d_in, const int* in_sizes, int n_in,
                              void* d_out, int out_size) {
    const float* x    = (const float*)d_in[0];
    const float* pos  = (const float*)d_in[1];
    const float* ea   = (const float*)d_in[2];
    const int*   ei   = (const int*)  d_in[3];
    const int*   bat  = (const int*)  d_in[4];
    const float* c1w1 = (const float*)d_in[5];
    const float* c1b1 = (const float*)d_in[6];
    const float* c1w2 = (const float*)d_in[7];
    const float* c1b2 = (const float*)d_in[8];
    const float* c1r  = (const float*)d_in[9];
    const float* c1b  = (const float*)d_in[10];
    const float* c2w1 = (const float*)d_in[11];
    const float* c2b1 = (const float*)d_in[12];
    const float* c2w2 = (const float*)d_in[13];
    const float* c2b2 = (const float*)d_in[14];
    const float* c2r  = (const float*)d_in[15];
    const float* c2b  = (const float*)d_in[16];
    const float* c3w1 = (const float*)d_in[17];
    const float* c3b1 = (const float*)d_in[18];
    const float* c3w2 = (const float*)d_in[19];
    const float* c3b2 = (const float*)d_in[20];
    const float* c3r  = (const float*)d_in[21];
    const float* c3b  = (const float*)d_in[22];
    const float* f1w  = (const float*)d_in[23];
    const float* f1b  = (const float*)d_in[24];
    const float* ow   = (const float*)d_in[25];
    const float* ob   = (const float*)d_in[26];
    float* out = (float*)d_out;

    void *pX0, *pA, *pB, *pG, *pBT, *pxb, *pagg, *ph, *ppool;
    cudaGetSymbolAddress(&pX0, g_X0);
    cudaGetSymbolAddress(&pA, g_bufA);
    cudaGetSymbolAddress(&pB, g_bufB);
    cudaGetSymbolAddress(&pG, g_G);
    cudaGetSymbolAddress(&pBT, g_BT);
    cudaGetSymbolAddress(&pxb, g_xb);
    cudaGetSymbolAddress(&pagg, g_agg);
    cudaGetSymbolAddress(&ph, g_h);
    cudaGetSymbolAddress(&ppool, g_pool);
    float* X0  = (float*)pX0;
    float* bufA= (float*)pA;
    float* bufB= (float*)pB;
    __half* G  = (__half*)pG;
    float* BT  = (float*)pBT;
    float* xb  = (float*)pxb;
    float* agg = (float*)pagg;
    float* h   = (float*)ph;
    float* pool= (float*)ppool;

    build_x0<<<(N_NODES * F0 + 255) / 256, 256>>>(x, pos);
    init_deg<<<(N_NODES + 255) / 256, 256>>>();
    bucket_build<<<(N_EDGES + 255) / 256, 256>>>(ei);

    // layer 1: 16 -> 90
    run_layer(X0, bufA, F0, HH, c1w1, c1b1, c1w2, c1b2, c1r, c1b, ea, ei, G, BT, xb, agg, h);
    // layer 2: 90 -> 90
    run_layer(bufA, bufB, HH, HH, c2w1, c2b1, c2w2, c2b2, c2r, c2b, ea, ei, G, BT, xb, agg, h);
    // layer 3: 90 -> 45
    run_layer(bufB, bufA, HH, H2, c3w1, c3b1, c3w2, c3b2, c3r, c3b, ea, ei, G, BT, xb, agg, h);

    zero_f<<<(NGR * H2 + 255) / 256, 256>>>(pool, NGR * H2);
    pool_add<<<(N_NODES * H2 + 255) / 256, 256>>>(bat, bufA);
    head_k<<<NGR, 96>>>(f1w, f1b, ow, ob, out);
}

// round 7
// speedup vs baseline: 1.7857x; 1.0148x over previous
#include <cuda_runtime.h>
#include <cuda_fp16.h>
#include <math.h>
#include <stdint.h>

#define N_NODES 16000
#define N_EDGES 64000
#define HH 90
#define F0 16
#define EF 8
#define NGR 512
#define H2 45
#define CAP 64
#define NCP_MAX 8192
#define KP_MAX 96
#define CK 32
#define LDC 36

// ---------------- scratch (__device__ globals; no allocation) ----------------
__device__ float g_X0[N_NODES * F0];
__device__ float g_bufA[N_NODES * HH];
__device__ float g_bufB[N_NODES * HH];
__device__ float g_msg[(size_t)N_EDGES * HH];               // 23 MB
__device__ __half g_G[(size_t)N_NODES * NCP_MAX];           // 262 MB (fp16)
__device__ float g_BT[NCP_MAX * KP_MAX];                    // B^T [ncp][kp], zero-padded
__device__ float g_agg[N_NODES * HH];                       // overflow-only accumulator
__device__ float g_pool[NGR * H2];
__device__ int   g_deg[N_NODES],  g_bucket[N_NODES * CAP];   // src buckets
__device__ int   g_deg2[N_NODES], g_bucket2[N_NODES * CAP];  // dst buckets
__device__ int   g_ovfS[N_EDGES], g_ovfD[N_EDGES];
__device__ int   g_ovfnS, g_ovfnD;

// ---------------- tf32 mma.sync GEMM: G[M x ncp](fp16) = A[M x in_c] @ BT^T ----------------
__global__ __launch_bounds__(256, 2)
void mma_gemm(const float* __restrict__ A, const float* __restrict__ BT,
              __half* __restrict__ C, int in_c, int ncp, int kp) {
    __shared__ uint32_t As[128 * LDC];
    __shared__ uint32_t Bs[128 * LDC];

    const int tid = threadIdx.x;
    const int lane = tid & 31, wid = tid >> 5;
    const int rowBase = blockIdx.y * 128, colBase = blockIdx.x * 128;
    const int warpRow = (wid & 3) * 32;
    const int warpCol = (wid >> 2) * 64;
    const int qr = lane >> 2, qk = lane & 3;

    float acc[2][8][4];
#pragma unroll
    for (int mt = 0; mt < 2; mt++)
#pragma unroll
        for (int nt = 0; nt < 8; nt++)
#pragma unroll
            for (int j = 0; j < 4; j++) acc[mt][nt][j] = 0.f;

    for (int kc = 0; kc < kp; kc += CK) {
        for (int idx = tid; idx < 128 * CK; idx += 256) {
            int row = idx >> 5, k = idx & 31;
            int gk = kc + k;
            float v = (gk < in_c) ? A[(size_t)(rowBase + row) * in_c + gk] : 0.f;
            uint32_t t;
            asm("cvt.rna.tf32.f32 %0, %1;" : "=r"(t) : "f"(v));
            As[row * LDC + k] = t;
        }
        for (int idx = tid; idx < 128 * CK; idx += 256) {
            int col = idx >> 5, k = idx & 31;
            float v = BT[(size_t)(colBase + col) * kp + kc + k];
            uint32_t t;
            asm("cvt.rna.tf32.f32 %0, %1;" : "=r"(t) : "f"(v));
            Bs[col * LDC + k] = t;
        }
        __syncthreads();

#pragma unroll
        for (int ks = 0; ks < CK; ks += 8) {
            uint32_t a[2][4];
#pragma unroll
            for (int mt = 0; mt < 2; mt++) {
                int r = warpRow + mt * 16 + qr;
                a[mt][0] = As[r * LDC + ks + qk];
                a[mt][1] = As[(r + 8) * LDC + ks + qk];
                a[mt][2] = As[r * LDC + ks + qk + 4];
                a[mt][3] = As[(r + 8) * LDC + ks + qk + 4];
            }
#pragma unroll
            for (int nt = 0; nt < 8; nt++) {
                int c = warpCol + nt * 8 + qr;
                uint32_t b0 = Bs[c * LDC + ks + qk];
                uint32_t b1 = Bs[c * LDC + ks + qk + 4];
#pragma unroll
                for (int mt = 0; mt < 2; mt++) {
                    asm volatile(
                        "mma.sync.aligned.m16n8k8.row.col.f32.tf32.tf32.f32 "
                        "{%0,%1,%2,%3}, {%4,%5,%6,%7}, {%8,%9}, {%0,%1,%2,%3};"
                        : "+f"(acc[mt][nt][0]), "+f"(acc[mt][nt][1]),
                          "+f"(acc[mt][nt][2]), "+f"(acc[mt][nt][3])
                        : "r"(a[mt][0]), "r"(a[mt][1]), "r"(a[mt][2]), "r"(a[mt][3]),
                          "r"(b0), "r"(b1));
                }
            }
        }
        __syncthreads();
    }

#pragma unroll
    for (int mt = 0; mt < 2; mt++) {
        int r = rowBase + warpRow + mt * 16 + qr;
#pragma unroll
        for (int nt = 0; nt < 8; nt++) {
            int c = colBase + warpCol + nt * 8 + qk * 2;
            __half2 v0 = __floats2half2_rn(acc[mt][nt][0], acc[mt][nt][1]);
            __half2 v1 = __floats2half2_rn(acc[mt][nt][2], acc[mt][nt][3]);
            *(__half2*)&C[(size_t)r * ncp + c] = v0;
            *(__half2*)&C[(size_t)(r + 8) * ncp + c] = v1;
        }
    }
}

// ---------------- utility kernels ----------------
__global__ void zero_f(float* p, int n) {
    int i = blockIdx.x * blockDim.x + threadIdx.x;
    if (i < n) p[i] = 0.f;
}

__global__ void init_deg() {
    int i = blockIdx.x * blockDim.x + threadIdx.x;
    if (i < N_NODES) { g_deg[i] = 0; g_deg2[i] = 0; }
    if (i == 0) { g_ovfnS = 0; g_ovfnD = 0; }
}

__global__ void build_x0(const float* __restrict__ x, const float* __restrict__ pos) {
    int i = blockIdx.x * blockDim.x + threadIdx.x;
    if (i >= N_NODES * F0) return;
    int n = i / F0, c = i % F0;
    g_X0[i] = (c < 13) ? x[n * 13 + c] : pos[n * 3 + (c - 13)];
}

__global__ void bucket_build(const int* __restrict__ ei) {
    int e = blockIdx.x * blockDim.x + threadIdx.x;
    if (e >= N_EDGES) return;
    int s = ei[e];
    int slot = atomicAdd(&g_deg[s], 1);
    if (slot < CAP) g_bucket[s * CAP + slot] = e;
    else            g_ovfS[atomicAdd(&g_ovfnS, 1)] = e;
    int t = ei[N_EDGES + e];
    int slot2 = atomicAdd(&g_deg2[t], 1);
    if (slot2 < CAP) g_bucket2[t * CAP + slot2] = e;
    else             g_ovfD[atomicAdd(&g_ovfnD, 1)] = e;
}

// BT[col][k]: cols [0, HH*out) from w2; cols [HH*out, HH*out+out) from b2; else 0
__global__ void buildBT(const float* __restrict__ w2, const float* __restrict__ b2,
                        float* __restrict__ BT, int in_c, int out_c, int ncp, int kp) {
    int idx = blockIdx.x * blockDim.x + threadIdx.x;
    if (idx >= ncp * kp) return;
    int col = idx / kp, k = idx - col * kp;
    float v = 0.f;
    if (k < in_c) {
        if (col < HH * out_c) {
            int kk = col / out_c, o = col - kk * out_c;
            v = w2[((size_t)kk * in_c + k) * out_c + o];
        } else if (col < HH * out_c + out_c) {
            v = b2[k * out_c + (col - HH * out_c)];
        }
    }
    BT[idx] = v;
}

// ---------------- per-src-node: edge MLP + message (no atomics) ----------------
__global__ void msg2(const int* __restrict__ ei, const float* __restrict__ ea,
                     const float* __restrict__ w1, const float* __restrict__ b1,
                     int out_c, int strideG,
                     const __half* __restrict__ G, float* __restrict__ msg) {
    int n = blockIdx.x;
    int d = g_deg[n];
    if (d == 0) return;
    if (d > CAP) d = CAP;
    __shared__ float w1s[EF][HH];
    __shared__ float b1s[HH];
    __shared__ float eas[8][EF];
    __shared__ float hs[8][HH];
    __shared__ int eS[8];
    int tid = threadIdx.x;
    for (int t = tid; t < EF * HH; t += blockDim.x) w1s[t / HH][t % HH] = w1[t];
    for (int t = tid; t < HH; t += blockDim.x) b1s[t] = b1[t];
    const __half* Grow = &g_G[0] == G ? &G[(size_t)n * strideG] : &G[(size_t)n * strideG];
    float xbv = (tid < out_c) ? __half2float(Grow[HH * out_c + tid]) : 0.f;

    for (int base = 0; base < d; base += 8) {
        int m = min(8, d - base);
        __syncthreads();
        if (tid < m) eS[tid] = g_bucket[n * CAP + base + tid];
        __syncthreads();
        for (int t = tid; t < m * EF; t += blockDim.x)
            eas[t >> 3][t & 7] = ea[eS[t >> 3] * EF + (t & 7)];
        __syncthreads();
        int k = tid;
        if (k < HH) {
            for (int j = 0; j < m; j++) {
                float s = b1s[k];
#pragma unroll
                for (int q = 0; q < EF; q++) s = fmaf(eas[j][q], w1s[q][k], s);
                hs[j][k] = fmaxf(s, 0.f);
            }
        }
        __syncthreads();
        int o = tid;
        if (o < out_c) {
            float acc[8];
#pragma unroll
            for (int j = 0; j < 8; j++) acc[j] = 0.f;
            for (int kk = 0; kk < HH; kk++) {
                float g = __half2float(Grow[kk * out_c + o]);
#pragma unroll
                for (int j = 0; j < 8; j++) acc[j] = fmaf(hs[j][kk], g, acc[j]);
            }
            for (int j = 0; j < m; j++)
                msg[(size_t)eS[j] * out_c + o] = acc[j] + xbv;
        }
    }
}

// src-overflow fallback (normally zero iterations)
__global__ void msg_ovfS(const int* __restrict__ ei, const float* __restrict__ ea,
                         const float* __restrict__ w1, const float* __restrict__ b1,
                         int out_c, int strideG,
                         const __half* __restrict__ G, float* __restrict__ msg) {
    __shared__ float hs[HH];
    for (int idx = blockIdx.x; idx < g_ovfnS; idx += gridDim.x) {
        int e = g_ovfS[idx];
        int n = ei[e];
        int k = threadIdx.x;
        if (k < HH) {
            float s = b1[k];
#pragma unroll
            for (int q = 0; q < EF; q++) s = fmaf(ea[e * EF + q], w1[q * HH + k], s);
            hs[k] = fmaxf(s, 0.f);
        }
        __syncthreads();
        const __half* Grow = &G[(size_t)n * strideG];
        int o = threadIdx.x;
        if (o < out_c) {
            float acc = __half2float(Grow[HH * out_c + o]);
            for (int kk = 0; kk < HH; kk++)
                acc = fmaf(hs[kk], __half2float(Grow[kk * out_c + o]), acc);
            msg[(size_t)e * out_c + o] = acc;
        }
        __syncthreads();
    }
}

// dst-overflow fallback (normally zero iterations)
__global__ void agg_ovfD(const int* __restrict__ ei, int out_c,
                         const float* __restrict__ msg, float* __restrict__ agg) {
    for (int idx = blockIdx.x; idx < g_ovfnD; idx += gridDim.x) {
        int e = g_ovfD[idx];
        int t = ei[N_EDGES + e];
        int o = threadIdx.x;
        if (o < out_c) atomicAdd(&agg[t * out_c + o], msg[(size_t)e * out_c + o]);
    }
}

// per-dst-node: gather msgs + root + bias + relu (fused finalize; optional pool)
__global__ void aggfin(const float* __restrict__ Xin, float* __restrict__ Xout,
                       const float* __restrict__ root, const float* __restrict__ bias,
                       const float* __restrict__ agg, const float* __restrict__ msg,
                       int in_c, int out_c,
                       const int* __restrict__ batch, float* __restrict__ pool) {
    int n = blockIdx.x;
    __shared__ float xs[HH];
    __shared__ int eS[CAP];
    int tid = threadIdx.x;
    for (int t = tid; t < in_c; t += blockDim.x) xs[t] = Xin[n * in_c + t];
    int d = g_deg2[n];
    if (d > CAP) d = CAP;
    for (int t = tid; t < d; t += blockDim.x) eS[t] = g_bucket2[n * CAP + t];
    __syncthreads();
    int o = tid;
    if (o < out_c) {
        float acc = agg[n * out_c + o] + bias[o];
        for (int j = 0; j < d; j++)
            acc += msg[(size_t)eS[j] * out_c + o];
        for (int i = 0; i < in_c; i++)
            acc = fmaf(xs[i], __ldg(&root[i * out_c + o]), acc);
        acc = fmaxf(acc, 0.f);
        if (pool) atomicAdd(&pool[batch[n] * out_c + o], acc);
        else      Xout[n * out_c + o] = acc;
    }
}

__global__ void head_k(const float* __restrict__ fc1w, const float* __restrict__ fc1b,
                       const float* __restrict__ outw, const float* __restrict__ outb,
                       float* __restrict__ out) {
    int g = blockIdx.x;
    __shared__ float ps[H2];
    __shared__ float fs[HH];
    for (int t = threadIdx.x; t < H2; t += blockDim.x) ps[t] = g_pool[g * H2 + t];
    __syncthreads();
    int o = threadIdx.x;
    if (o < HH) {
        float a = fc1b[o];
        for (int i = 0; i < H2; i++) a = fmaf(ps[i], fc1w[i * HH + o], a);
        fs[o] = fmaxf(a, 0.f);
    }
    __syncthreads();
    if (threadIdx.x == 0) {
        float s = outb[0];
        for (int q = 0; q < HH; q++) s = fmaf(fs[q], outw[q], s);
        out[g] = s;
    }
}

// ---------------- host orchestration ----------------
static void run_layer(const float* Xin, float* Xout, int in_c, int out_c,
                      const float* w1, const float* b1, const float* w2, const float* b2,
                      const float* root, const float* bias,
                      const float* ea, const int* ei,
                      __half* G, float* BT, float* agg, float* msg,
                      const int* batch, float* pool) {
    int ncp = (HH * out_c + out_c + 127) & ~127;   // 8192 / 8192 / 4096
    int kp = ((in_c + 31) & ~31);                  // 32 / 96 / 96

    buildBT<<<(ncp * kp + 255) / 256, 256>>>(w2, b2, BT, in_c, out_c, ncp, kp);
    {
        dim3 gr(ncp / 128, N_NODES / 128);
        mma_gemm<<<gr, 256>>>(Xin, BT, G, in_c, ncp, kp);
    }
    msg2<<<N_NODES, 96>>>(ei, ea, w1, b1, out_c, ncp, G, msg);
    msg_ovfS<<<64, 96>>>(ei, ea, w1, b1, out_c, ncp, G, msg);
    zero_f<<<(N_NODES * out_c + 255) / 256, 256>>>(agg, N_NODES * out_c);
    agg_ovfD<<<64, 96>>>(ei, out_c, msg, agg);
    aggfin<<<N_NODES, 96>>>(Xin, Xout, root, bias, agg, msg, in_c, out_c, batch, pool);
}

extern "C" void kernel_launch(void* const* d_in, const int* in_sizes, int n_in,
                              void* d_out, int out_size) {
    const float* x    = (const float*)d_in[0];
    const float* pos  = (const float*)d_in[1];
    const float* ea   = (const float*)d_in[2];
    const int*   ei   = (const int*)  d_in[3];
    const int*   bat  = (const int*)  d_in[4];
    const float* c1w1 = (const float*)d_in[5];
    const float* c1b1 = (const float*)d_in[6];
    const float* c1w2 = (const float*)d_in[7];
    const float* c1b2 = (const float*)d_in[8];
    const float* c1r  = (const float*)d_in[9];
    const float* c1b  = (const float*)d_in[10];
    const float* c2w1 = (const float*)d_in[11];
    const float* c2b1 = (const float*)d_in[12];
    const float* c2w2 = (const float*)d_in[13];
    const float* c2b2 = (const float*)d_in[14];
    const float* c2r  = (const float*)d_in[15];
    const float* c2b  = (const float*)d_in[16];
    const float* c3w1 = (const float*)d_in[17];
    const float* c3b1 = (const float*)d_in[18];
    const float* c3w2 = (const float*)d_in[19];
    const float* c3b2 = (const float*)d_in[20];
    const float* c3r  = (const float*)d_in[21];
    const float* c3b  = (const float*)d_in[22];
    const float* f1w  = (const float*)d_in[23];
    const float* f1b  = (const float*)d_in[24];
    const float* ow   = (const float*)d_in[25];
    const float* ob   = (const float*)d_in[26];
    float* out = (float*)d_out;

    void *pX0, *pA, *pB, *pG, *pBT, *pagg, *pmsg, *ppool;
    cudaGetSymbolAddress(&pX0, g_X0);
    cudaGetSymbolAddress(&pA, g_bufA);
    cudaGetSymbolAddress(&pB, g_bufB);
    cudaGetSymbolAddress(&pG, g_G);
    cudaGetSymbolAddress(&pBT, g_BT);
    cudaGetSymbolAddress(&pagg, g_agg);
    cudaGetSymbolAddress(&pmsg, g_msg);
    cudaGetSymbolAddress(&ppool, g_pool);
    float* X0  = (float*)pX0;
    float* bufA= (float*)pA;
    float* bufB= (float*)pB;
    __half* G  = (__half*)pG;
    float* BT  = (float*)pBT;
    float* agg = (float*)pagg;
    float* msg = (float*)pmsg;
    float* pool= (float*)ppool;

    build_x0<<<(N_NODES * F0 + 255) / 256, 256>>>(x, pos);
    init_deg<<<(N_NODES + 255) / 256, 256>>>();
    bucket_build<<<(N_EDGES + 255) / 256, 256>>>(ei);
    zero_f<<<(NGR * H2 + 255) / 256, 256>>>(pool, NGR * H2);

    // layer 1: 16 -> 90
    run_layer(X0, bufA, F0, HH, c1w1, c1b1, c1w2, c1b2, c1r, c1b, ea, ei,
              G, BT, agg, msg, nullptr, nullptr);
    // layer 2: 90 -> 90
    run_layer(bufA, bufB, HH, HH, c2w1, c2b1, c2w2, c2b2, c2r, c2b, ea, ei,
              G, BT, agg, msg, nullptr, nullptr);
    // layer 3: 90 -> 45, fused global_add_pool
    run_layer(bufB, bufA, HH, H2, c3w1, c3b1, c3w2, c3b2, c3r, c3b, ea, ei,
              G, BT, agg, msg, bat, pool);

    head_k<<<NGR, 96>>>(f1w, f1b, ow, ob, out);
}

// round 8
// speedup vs baseline: 2.3529x; 1.3176x over previous
#include <cuda_runtime.h>
#include <cuda_fp16.h>
#include <math.h>
#include <stdint.h>

#define N_NODES 16000
#define N_EDGES 64000
#define HH 90
#define F0 16
#define EF 8
#define NGR 512
#define H2 45
#define CAP 64
#define NCP_MAX 8192
#define KP_MAX 96
#define CK 32
#define LDH 40

// ---------------- scratch (__device__ globals; no allocation) ----------------
__device__ float g_X0[N_NODES * F0];
__device__ float g_bufA[N_NODES * HH];
__device__ float g_bufB[N_NODES * HH];
__device__ float g_msg[(size_t)N_EDGES * HH];                 // 23 MB
__device__ __half g_G[(size_t)N_NODES * NCP_MAX];             // 262 MB (fp16)
__device__ __half g_Ah[N_NODES * KP_MAX];                     // padded half A
__device__ __half g_BTh[NCP_MAX * KP_MAX];                    // padded half B^T
__device__ float g_agg[N_NODES * HH];                         // overflow-only accumulator
__device__ float g_pool[NGR * H2];
__device__ int   g_deg[N_NODES],  g_bucket[N_NODES * CAP];    // src buckets
__device__ int   g_deg2[N_NODES], g_bucket2[N_NODES * CAP];   // dst buckets
__device__ int   g_ovfS[N_EDGES], g_ovfD[N_EDGES];
__device__ int   g_ovfnS, g_ovfnD;

// ---------------- fp16 mma.sync GEMM: G[M x ncp](fp16) = Ah[M x kp] @ BTh^T ----------------
// Ah [M][kp] half zero-padded; BTh [ncp][kp] half zero-padded; M%128==0, ncp%128==0, kp%32==0.
__global__ __launch_bounds__(256, 2)
void mma_gemm_h(const __half* __restrict__ A, const __half* __restrict__ BT,
                __half* __restrict__ C, int ncp, int kp) {
    __shared__ __half As[128 * LDH];
    __shared__ __half Bs[128 * LDH];

    const int tid = threadIdx.x;
    const int lane = tid & 31, wid = tid >> 5;
    const int rowBase = blockIdx.y * 128, colBase = blockIdx.x * 128;
    const int warpRow = (wid & 3) * 32;   // 4 row groups of 32
    const int warpCol = (wid >> 2) * 64;  // 2 col groups of 64
    const int qr = lane >> 2, qk = lane & 3;

    float acc[2][8][4];
#pragma unroll
    for (int mt = 0; mt < 2; mt++)
#pragma unroll
        for (int nt = 0; nt < 8; nt++)
#pragma unroll
            for (int j = 0; j < 4; j++) acc[mt][nt][j] = 0.f;

    for (int kc = 0; kc < kp; kc += CK) {
        // fill A: 128 rows x 32 halves; 512 16B-tasks over 256 threads
#pragma unroll
        for (int i = 0; i < 2; i++) {
            int t = tid + i * 256;
            int row = t >> 2, k0 = (t & 3) * 8;
            uint4 v = *(const uint4*)&A[(size_t)(rowBase + row) * kp + kc + k0];
            *(uint4*)&As[row * LDH + k0] = v;
        }
#pragma unroll
        for (int i = 0; i < 2; i++) {
            int t = tid + i * 256;
            int row = t >> 2, k0 = (t & 3) * 8;
            uint4 v = *(const uint4*)&BT[(size_t)(colBase + row) * kp + kc + k0];
            *(uint4*)&Bs[row * LDH + k0] = v;
        }
        __syncthreads();

#pragma unroll
        for (int ks = 0; ks < CK; ks += 16) {
            uint32_t a[2][4];
#pragma unroll
            for (int mt = 0; mt < 2; mt++) {
                int r = warpRow + mt * 16 + qr;
                a[mt][0] = *(const uint32_t*)&As[r * LDH + ks + 2 * qk];
                a[mt][1] = *(const uint32_t*)&As[(r + 8) * LDH + ks + 2 * qk];
                a[mt][2] = *(const uint32_t*)&As[r * LDH + ks + 2 * qk + 8];
                a[mt][3] = *(const uint32_t*)&As[(r + 8) * LDH + ks + 2 * qk + 8];
            }
#pragma unroll
            for (int nt = 0; nt < 8; nt++) {
                int c = warpCol + nt * 8 + qr;
                uint32_t b0 = *(const uint32_t*)&Bs[c * LDH + ks + 2 * qk];
                uint32_t b1 = *(const uint32_t*)&Bs[c * LDH + ks + 2 * qk + 8];
#pragma unroll
                for (int mt = 0; mt < 2; mt++) {
                    asm volatile(
                        "mma.sync.aligned.m16n8k16.row.col.f32.f16.f16.f32 "
                        "{%0,%1,%2,%3}, {%4,%5,%6,%7}, {%8,%9}, {%0,%1,%2,%3};"
                        : "+f"(acc[mt][nt][0]), "+f"(acc[mt][nt][1]),
                          "+f"(acc[mt][nt][2]), "+f"(acc[mt][nt][3])
                        : "r"(a[mt][0]), "r"(a[mt][1]), "r"(a[mt][2]), "r"(a[mt][3]),
                          "r"(b0), "r"(b1));
                }
            }
        }
        __syncthreads();
    }

#pragma unroll
    for (int mt = 0; mt < 2; mt++) {
        int r = rowBase + warpRow + mt * 16 + qr;
#pragma unroll
        for (int nt = 0; nt < 8; nt++) {
            int c = colBase + warpCol + nt * 8 + qk * 2;
            __half2 v0 = __floats2half2_rn(acc[mt][nt][0], acc[mt][nt][1]);
            __half2 v1 = __floats2half2_rn(acc[mt][nt][2], acc[mt][nt][3]);
            *(__half2*)&C[(size_t)r * ncp + c] = v0;
            *(__half2*)&C[(size_t)(r + 8) * ncp + c] = v1;
        }
    }
}

// ---------------- utility kernels ----------------
__global__ void zero_f(float* p, int n) {
    int i = blockIdx.x * blockDim.x + threadIdx.x;
    if (i < n) p[i] = 0.f;
}

__global__ void init_deg() {
    int i = blockIdx.x * blockDim.x + threadIdx.x;
    if (i < N_NODES) { g_deg[i] = 0; g_deg2[i] = 0; }
    if (i == 0) { g_ovfnS = 0; g_ovfnD = 0; }
}

__global__ void build_x0(const float* __restrict__ x, const float* __restrict__ pos) {
    int i = blockIdx.x * blockDim.x + threadIdx.x;
    if (i >= N_NODES * F0) return;
    int n = i / F0, c = i % F0;
    g_X0[i] = (c < 13) ? x[n * 13 + c] : pos[n * 3 + (c - 13)];
}

__global__ void bucket_build(const int* __restrict__ ei) {
    int e = blockIdx.x * blockDim.x + threadIdx.x;
    if (e >= N_EDGES) return;
    int s = ei[e];
    int slot = atomicAdd(&g_deg[s], 1);
    if (slot < CAP) g_bucket[s * CAP + slot] = e;
    else            g_ovfS[atomicAdd(&g_ovfnS, 1)] = e;
    int t = ei[N_EDGES + e];
    int slot2 = atomicAdd(&g_deg2[t], 1);
    if (slot2 < CAP) g_bucket2[t * CAP + slot2] = e;
    else             g_ovfD[atomicAdd(&g_ovfnD, 1)] = e;
}

// padded half A: Ah[n][k] = (k < in_c) ? Xin[n][k] : 0
__global__ void padX(const float* __restrict__ Xin, __half* __restrict__ Ah,
                     int in_c, int kp) {
    int idx = blockIdx.x * blockDim.x + threadIdx.x;
    if (idx >= N_NODES * kp) return;
    int n = idx / kp, k = idx - n * kp;
    Ah[idx] = __float2half((k < in_c) ? Xin[n * in_c + k] : 0.f);
}

// half BT: cols [0, HH*out) from w2; cols [HH*out, HH*out+out) from b2; else 0
__global__ void buildBT(const float* __restrict__ w2, const float* __restrict__ b2,
                        __half* __restrict__ BT, int in_c, int out_c, int ncp, int kp) {
    int idx = blockIdx.x * blockDim.x + threadIdx.x;
    if (idx >= ncp * kp) return;
    int col = idx / kp, k = idx - col * kp;
    float v = 0.f;
    if (k < in_c) {
        if (col < HH * out_c) {
            int kk = col / out_c, o = col - kk * out_c;
            v = w2[((size_t)kk * in_c + k) * out_c + o];
        } else if (col < HH * out_c + out_c) {
            v = b2[k * out_c + (col - HH * out_c)];
        }
    }
    BT[idx] = __float2half(v);
}

// ---------------- per-src-node: edge MLP + message (no atomics) ----------------
__global__ void msg2(const int* __restrict__ ei, const float* __restrict__ ea,
                     const float* __restrict__ w1, const float* __restrict__ b1,
                     int out_c, int strideG,
                     const __half* __restrict__ G, float* __restrict__ msg) {
    int n = blockIdx.x;
    int d = g_deg[n];
    if (d == 0) return;
    if (d > CAP) d = CAP;
    __shared__ float w1s[EF][HH];
    __shared__ float b1s[HH];
    __shared__ float eas[8][EF];
    __shared__ float hs[8][HH];
    __shared__ int eS[8];
    int tid = threadIdx.x;
    for (int t = tid; t < EF * HH; t += blockDim.x) w1s[t / HH][t % HH] = w1[t];
    for (int t = tid; t < HH; t += blockDim.x) b1s[t] = b1[t];
    const __half* Grow = &G[(size_t)n * strideG];
    float xbv = (tid < out_c) ? __half2float(Grow[HH * out_c + tid]) : 0.f;

    for (int base = 0; base < d; base += 8) {
        int m = min(8, d - base);
        __syncthreads();
        if (tid < m) eS[tid] = g_bucket[n * CAP + base + tid];
        __syncthreads();
        for (int t = tid; t < m * EF; t += blockDim.x)
            eas[t >> 3][t & 7] = ea[eS[t >> 3] * EF + (t & 7)];
        __syncthreads();
        int k = tid;
        if (k < HH) {
            for (int j = 0; j < m; j++) {
                float s = b1s[k];
#pragma unroll
                for (int q = 0; q < EF; q++) s = fmaf(eas[j][q], w1s[q][k], s);
                hs[j][k] = fmaxf(s, 0.f);
            }
        }
        __syncthreads();
        int o = tid;
        if (o < out_c) {
            float acc[8];
#pragma unroll
            for (int j = 0; j < 8; j++) acc[j] = 0.f;
            for (int kk = 0; kk < HH; kk++) {
                float g = __half2float(Grow[kk * out_c + o]);
#pragma unroll
                for (int j = 0; j < 8; j++) acc[j] = fmaf(hs[j][kk], g, acc[j]);
            }
            for (int j = 0; j < m; j++)
                msg[(size_t)eS[j] * out_c + o] = acc[j] + xbv;
        }
    }
}

// src-overflow fallback (normally zero iterations)
__global__ void msg_ovfS(const int* __restrict__ ei, const float* __restrict__ ea,
                         const float* __restrict__ w1, const float* __restrict__ b1,
                         int out_c, int strideG,
                         const __half* __restrict__ G, float* __restrict__ msg) {
    __shared__ float hs[HH];
    for (int idx = blockIdx.x; idx < g_ovfnS; idx += gridDim.x) {
        int e = g_ovfS[idx];
        int n = ei[e];
        int k = threadIdx.x;
        if (k < HH) {
            float s = b1[k];
#pragma unroll
            for (int q = 0; q < EF; q++) s = fmaf(ea[e * EF + q], w1[q * HH + k], s);
            hs[k] = fmaxf(s, 0.f);
        }
        __syncthreads();
        const __half* Grow = &G[(size_t)n * strideG];
        int o = threadIdx.x;
        if (o < out_c) {
            float acc = __half2float(Grow[HH * out_c + o]);
            for (int kk = 0; kk < HH; kk++)
                acc = fmaf(hs[kk], __half2float(Grow[kk * out_c + o]), acc);
            msg[(size_t)e * out_c + o] = acc;
        }
        __syncthreads();
    }
}

// dst-overflow fallback (normally zero iterations)
__global__ void agg_ovfD(const int* __restrict__ ei, int out_c,
                         const float* __restrict__ msg, float* __restrict__ agg) {
    for (int idx = blockIdx.x; idx < g_ovfnD; idx += gridDim.x) {
        int e = g_ovfD[idx];
        int t = ei[N_EDGES + e];
        int o = threadIdx.x;
        if (o < out_c) atomicAdd(&agg[t * out_c + o], msg[(size_t)e * out_c + o]);
    }
}

// per-dst-node: gather msgs + root + bias + relu (fused finalize; optional pool)
__global__ void aggfin(const float* __restrict__ Xin, float* __restrict__ Xout,
                       const float* __restrict__ root, const float* __restrict__ bias,
                       const float* __restrict__ agg, const float* __restrict__ msg,
                       int in_c, int out_c,
                       const int* __restrict__ batch, float* __restrict__ pool) {
    int n = blockIdx.x;
    __shared__ float xs[HH];
    __shared__ int eS[CAP];
    int tid = threadIdx.x;
    for (int t = tid; t < in_c; t += blockDim.x) xs[t] = Xin[n * in_c + t];
    int d = g_deg2[n];
    if (d > CAP) d = CAP;
    for (int t = tid; t < d; t += blockDim.x) eS[t] = g_bucket2[n * CAP + t];
    __syncthreads();
    int o = tid;
    if (o < out_c) {
        float acc = agg[n * out_c + o] + bias[o];
        for (int j = 0; j < d; j++)
            acc += msg[(size_t)eS[j] * out_c + o];
        for (int i = 0; i < in_c; i++)
            acc = fmaf(xs[i], __ldg(&root[i * out_c + o]), acc);
        acc = fmaxf(acc, 0.f);
        if (pool) atomicAdd(&pool[batch[n] * out_c + o], acc);
        else      Xout[n * out_c + o] = acc;
    }
}

__global__ void head_k(const float* __restrict__ fc1w, const float* __restrict__ fc1b,
                       const float* __restrict__ outw, const float* __restrict__ outb,
                       float* __restrict__ out) {
    int g = blockIdx.x;
    __shared__ float ps[H2];
    __shared__ float fs[HH];
    for (int t = threadIdx.x; t < H2; t += blockDim.x) ps[t] = g_pool[g * H2 + t];
    __syncthreads();
    int o = threadIdx.x;
    if (o < HH) {
        float a = fc1b[o];
        for (int i = 0; i < H2; i++) a = fmaf(ps[i], fc1w[i * HH + o], a);
        fs[o] = fmaxf(a, 0.f);
    }
    __syncthreads();
    if (threadIdx.x == 0) {
        float s = outb[0];
        for (int q = 0; q < HH; q++) s = fmaf(fs[q], outw[q], s);
        out[g] = s;
    }
}

// ---------------- host orchestration ----------------
static void run_layer(const float* Xin, float* Xout, int in_c, int out_c,
                      const float* w1, const float* b1, const float* w2, const float* b2,
                      const float* root, const float* bias,
                      const float* ea, const int* ei,
                      __half* G, __half* Ah, __half* BTh, float* agg, float* msg,
                      const int* batch, float* pool) {
    int ncp = (HH * out_c + out_c + 127) & ~127;   // 8192 / 8192 / 4096
    int kp = ((in_c + 31) & ~31);                  // 32 / 96 / 96

    padX<<<(N_NODES * kp + 255) / 256, 256>>>(Xin, Ah, in_c, kp);
    buildBT<<<(ncp * kp + 255) / 256, 256>>>(w2, b2, BTh, in_c, out_c, ncp, kp);
    {
        dim3 gr(ncp / 128, N_NODES / 128);
        mma_gemm_h<<<gr, 256>>>(Ah, BTh, G, ncp, kp);
    }
    msg2<<<N_NODES, 96>>>(ei, ea, w1, b1, out_c, ncp, G, msg);
    msg_ovfS<<<64, 96>>>(ei, ea, w1, b1, out_c, ncp, G, msg);
    zero_f<<<(N_NODES * out_c + 255) / 256, 256>>>(agg, N_NODES * out_c);
    agg_ovfD<<<64, 96>>>(ei, out_c, msg, agg);
    aggfin<<<N_NODES, 96>>>(Xin, Xout, root, bias, agg, msg, in_c, out_c, batch, pool);
}

extern "C" void kernel_launch(void* const* d_in, const int* in_sizes, int n_in,
                              void* d_out, int out_size) {
    const float* x    = (const float*)d_in[0];
    const float* pos  = (const float*)d_in[1];
    const float* ea   = (const float*)d_in[2];
    const int*   ei   = (const int*)  d_in[3];
    const int*   bat  = (const int*)  d_in[4];
    const float* c1w1 = (const float*)d_in[5];
    const float* c1b1 = (const float*)d_in[6];
    const float* c1w2 = (const float*)d_in[7];
    const float* c1b2 = (const float*)d_in[8];
    const float* c1r  = (const float*)d_in[9];
    const float* c1b  = (const float*)d_in[10];
    const float* c2w1 = (const float*)d_in[11];
    const float* c2b1 = (const float*)d_in[12];
    const float* c2w2 = (const float*)d_in[13];
    const float* c2b2 = (const float*)d_in[14];
    const float* c2r  = (const float*)d_in[15];
    const float* c2b  = (const float*)d_in[16];
    const float* c3w1 = (const float*)d_in[17];
    const float* c3b1 = (const float*)d_in[18];
    const float* c3w2 = (const float*)d_in[19];
    const float* c3b2 = (const float*)d_in[20];
    const float* c3r  = (const float*)d_in[21];
    const float* c3b  = (const float*)d_in[22];
    const float* f1w  = (const float*)d_in[23];
    const float* f1b  = (const float*)d_in[24];
    const float* ow   = (const float*)d_in[25];
    const float* ob   = (const float*)d_in[26];
    float* out = (float*)d_out;

    void *pX0, *pA, *pB, *pG, *pAh, *pBTh, *pagg, *pmsg, *ppool;
    cudaGetSymbolAddress(&pX0, g_X0);
    cudaGetSymbolAddress(&pA, g_bufA);
    cudaGetSymbolAddress(&pB, g_bufB);
    cudaGetSymbolAddress(&pG, g_G);
    cudaGetSymbolAddress(&pAh, g_Ah);
    cudaGetSymbolAddress(&pBTh, g_BTh);
    cudaGetSymbolAddress(&pagg, g_agg);
    cudaGetSymbolAddress(&pmsg, g_msg);
    cudaGetSymbolAddress(&ppool, g_pool);
    float* X0  = (float*)pX0;
    float* bufA= (float*)pA;
    float* bufB= (float*)pB;
    __half* G  = (__half*)pG;
    __half* Ah = (__half*)pAh;
    __half* BTh= (__half*)pBTh;
    float* agg = (float*)pagg;
    float* msg = (float*)pmsg;
    float* pool= (float*)ppool;

    build_x0<<<(N_NODES * F0 + 255) / 256, 256>>>(x, pos);
    init_deg<<<(N_NODES + 255) / 256, 256>>>();
    bucket_build<<<(N_EDGES + 255) / 256, 256>>>(ei);
    zero_f<<<(NGR * H2 + 255) / 256, 256>>>(pool, NGR * H2);

    // layer 1: 16 -> 90
    run_layer(X0, bufA, F0, HH, c1w1, c1b1, c1w2, c1b2, c1r, c1b, ea, ei,
              G, Ah, BTh, agg, msg, nullptr, nullptr);
    // layer 2: 90 -> 90
    run_layer(bufA, bufB, HH, HH, c2w1, c2b1, c2w2, c2b2, c2r, c2b, ea, ei,
              G, Ah, BTh, agg, msg, nullptr, nullptr);
    // layer 3: 90 -> 45, fused global_add_pool
    run_layer(bufB, bufA, HH, H2, c3w1, c3b1, c3w2, c3b2, c3r, c3b, ea, ei,
              G, Ah, BTh, agg, msg, bat, pool);

    head_k<<<NGR, 96>>>(f1w, f1b, ow, ob, out);
}

// round 9
// speedup vs baseline: 2.7687x; 1.1767x over previous
#include <cuda_runtime.h>
#include <cuda_fp16.h>
#include <math.h>
#include <stdint.h>

#define N_NODES 16000
#define N_EDGES 64000
#define HH 90
#define F0 16
#define EF 8
#define NGR 512
#define H2 45
#define CAP 64
#define NCP_MAX 8192
#define KP_MAX 96

// ---------------- scratch (__device__ globals; no allocation) ----------------
__device__ float g_X0[N_NODES * F0];
__device__ float g_bufA[N_NODES * HH];
__device__ float g_bufB[N_NODES * HH];
__device__ float g_msg[(size_t)N_EDGES * HH];                 // 23 MB
__device__ __half g_G[(size_t)N_NODES * NCP_MAX];             // 262 MB (fp16)
__device__ __half g_Ah[N_NODES * KP_MAX];                     // padded half A
__device__ __half g_BTh[NCP_MAX * KP_MAX];                    // padded half B^T
__device__ float g_agg[N_NODES * HH];                         // overflow-only accumulator
__device__ float g_pool[NGR * H2];
__device__ int   g_deg[N_NODES],  g_bucket[N_NODES * CAP];    // src buckets
__device__ int   g_deg2[N_NODES], g_bucket2[N_NODES * CAP];   // dst buckets
__device__ int   g_ovfS[N_EDGES], g_ovfD[N_EDGES];
__device__ int   g_ovfnS, g_ovfnD;

__device__ __forceinline__ uint32_t smem_u32(const void* p) {
    return (uint32_t)__cvta_generic_to_shared(p);
}
__device__ __forceinline__ void cp16(uint32_t dst, const void* src) {
    asm volatile("cp.async.cg.shared.global [%0], [%1], 16;" :: "r"(dst), "l"(src));
}

// ---------------- fp16 mma.sync GEMM (single-shot cp.async): G = Ah @ BTh^T ----------------
// Ah [M][kp] half zero-padded; BTh [ncp][kp] half zero-padded; M%128==0, ncp%128==0, kp%32==0, kp<=96.
__global__ __launch_bounds__(256)
void mma_gemm_h(const __half* __restrict__ A, const __half* __restrict__ BT,
                __half* __restrict__ C, int ncp, int kp, int lda) {
    extern __shared__ __half sm[];
    __half* As = sm;
    __half* Bs = sm + 128 * lda;

    const int tid = threadIdx.x;
    const int lane = tid & 31, wid = tid >> 5;
    const int rowBase = blockIdx.y * 128, colBase = blockIdx.x * 128;
    const int warpRow = (wid & 3) * 32;
    const int warpCol = (wid >> 2) * 64;
    const int qr = lane >> 2, qk = lane & 3;

    // one-shot async fill of the full A and B tiles
    const int nvec = kp >> 3;             // uint4 per row
    for (int t = tid; t < 128 * nvec; t += 256) {
        int row = t / nvec, j = (t - row * nvec) * 8;
        cp16(smem_u32(&As[row * lda + j]), &A[(size_t)(rowBase + row) * kp + j]);
    }
    for (int t = tid; t < 128 * nvec; t += 256) {
        int row = t / nvec, j = (t - row * nvec) * 8;
        cp16(smem_u32(&Bs[row * lda + j]), &BT[(size_t)(colBase + row) * kp + j]);
    }
    asm volatile("cp.async.commit_group;");

    float acc[2][8][4];
#pragma unroll
    for (int mt = 0; mt < 2; mt++)
#pragma unroll
        for (int nt = 0; nt < 8; nt++)
#pragma unroll
            for (int j = 0; j < 4; j++) acc[mt][nt][j] = 0.f;

    asm volatile("cp.async.wait_group 0;");
    __syncthreads();

    for (int ks = 0; ks < kp; ks += 16) {
        uint32_t a[2][4];
#pragma unroll
        for (int mt = 0; mt < 2; mt++) {
            int r = warpRow + mt * 16 + qr;
            a[mt][0] = *(const uint32_t*)&As[r * lda + ks + 2 * qk];
            a[mt][1] = *(const uint32_t*)&As[(r + 8) * lda + ks + 2 * qk];
            a[mt][2] = *(const uint32_t*)&As[r * lda + ks + 2 * qk + 8];
            a[mt][3] = *(const uint32_t*)&As[(r + 8) * lda + ks + 2 * qk + 8];
        }
#pragma unroll
        for (int nt = 0; nt < 8; nt++) {
            int c = warpCol + nt * 8 + qr;
            uint32_t b0 = *(const uint32_t*)&Bs[c * lda + ks + 2 * qk];
            uint32_t b1 = *(const uint32_t*)&Bs[c * lda + ks + 2 * qk + 8];
#pragma unroll
            for (int mt = 0; mt < 2; mt++) {
                asm volatile(
                    "mma.sync.aligned.m16n8k16.row.col.f32.f16.f16.f32 "
                    "{%0,%1,%2,%3}, {%4,%5,%6,%7}, {%8,%9}, {%0,%1,%2,%3};"
                    : "+f"(acc[mt][nt][0]), "+f"(acc[mt][nt][1]),
                      "+f"(acc[mt][nt][2]), "+f"(acc[mt][nt][3])
                    : "r"(a[mt][0]), "r"(a[mt][1]), "r"(a[mt][2]), "r"(a[mt][3]),
                      "r"(b0), "r"(b1));
            }
        }
    }

#pragma unroll
    for (int mt = 0; mt < 2; mt++) {
        int r = rowBase + warpRow + mt * 16 + qr;
#pragma unroll
        for (int nt = 0; nt < 8; nt++) {
            int c = colBase + warpCol + nt * 8 + qk * 2;
            __half2 v0 = __floats2half2_rn(acc[mt][nt][0], acc[mt][nt][1]);
            __half2 v1 = __floats2half2_rn(acc[mt][nt][2], acc[mt][nt][3]);
            *(__half2*)&C[(size_t)r * ncp + c] = v0;
            *(__half2*)&C[(size_t)(r + 8) * ncp + c] = v1;
        }
    }
}

// ---------------- utility kernels ----------------
__global__ void zero_f(float* p, int n) {
    int i = blockIdx.x * blockDim.x + threadIdx.x;
    if (i < n) p[i] = 0.f;
}

__global__ void init_deg() {
    int i = blockIdx.x * blockDim.x + threadIdx.x;
    if (i < N_NODES) { g_deg[i] = 0; g_deg2[i] = 0; }
    if (i == 0) { g_ovfnS = 0; g_ovfnD = 0; }
}

__global__ void build_x0(const float* __restrict__ x, const float* __restrict__ pos) {
    int i = blockIdx.x * blockDim.x + threadIdx.x;
    if (i >= N_NODES * F0) return;
    int n = i / F0, c = i % F0;
    g_X0[i] = (c < 13) ? x[n * 13 + c] : pos[n * 3 + (c - 13)];
}

__global__ void bucket_build(const int* __restrict__ ei) {
    int e = blockIdx.x * blockDim.x + threadIdx.x;
    if (e >= N_EDGES) return;
    int s = ei[e];
    int slot = atomicAdd(&g_deg[s], 1);
    if (slot < CAP) g_bucket[s * CAP + slot] = e;
    else            g_ovfS[atomicAdd(&g_ovfnS, 1)] = e;
    int t = ei[N_EDGES + e];
    int slot2 = atomicAdd(&g_deg2[t], 1);
    if (slot2 < CAP) g_bucket2[t * CAP + slot2] = e;
    else             g_ovfD[atomicAdd(&g_ovfnD, 1)] = e;
}

// padded half A: Ah[n][k] = (k < in_c) ? Xin[n][k] : 0
__global__ void padX(const float* __restrict__ Xin, __half* __restrict__ Ah,
                     int in_c, int kp) {
    int idx = blockIdx.x * blockDim.x + threadIdx.x;
    if (idx >= N_NODES * kp) return;
    int n = idx / kp, k = idx - n * kp;
    Ah[idx] = __float2half((k < in_c) ? Xin[n * in_c + k] : 0.f);
}

// half BT: cols [0, HH*out) from w2; cols [HH*out, HH*out+out) from b2; else 0
__global__ void buildBT(const float* __restrict__ w2, const float* __restrict__ b2,
                        __half* __restrict__ BT, int in_c, int out_c, int ncp, int kp) {
    int idx = blockIdx.x * blockDim.x + threadIdx.x;
    if (idx >= ncp * kp) return;
    int col = idx / kp, k = idx - col * kp;
    float v = 0.f;
    if (k < in_c) {
        if (col < HH * out_c) {
            int kk = col / out_c, o = col - kk * out_c;
            v = w2[((size_t)kk * in_c + k) * out_c + o];
        } else if (col < HH * out_c + out_c) {
            v = b2[k * out_c + (col - HH * out_c)];
        }
    }
    BT[idx] = __float2half(v);
}

// ---------------- per-src-node: edge MLP + message (G row staged in smem) ----------------
__global__ void msg2(const int* __restrict__ ei, const float* __restrict__ ea,
                     const float* __restrict__ w1, const float* __restrict__ b1,
                     int out_c, int strideG,
                     const __half* __restrict__ G, float* __restrict__ msg) {
    int n = blockIdx.x;
    int d = g_deg[n];
    if (d == 0) return;
    if (d > CAP) d = CAP;
    __shared__ __half Gs[NCP_MAX];     // 16 KB
    __shared__ float w1s[EF][HH];
    __shared__ float b1s[HH];
    __shared__ float eas[8][EF];
    __shared__ float hs[8][HH];
    __shared__ int eS[8];
    int tid = threadIdx.x;

    // bulk-stage G row (coalesced uint4)
    const __half* Grow = &G[(size_t)n * strideG];
    int nvec = (HH * out_c + out_c + 7) >> 3;
    for (int t = tid; t < nvec; t += blockDim.x)
        *(uint4*)&Gs[t * 8] = *(const uint4*)&Grow[t * 8];
    for (int t = tid; t < EF * HH; t += blockDim.x) w1s[t / HH][t % HH] = w1[t];
    for (int t = tid; t < HH; t += blockDim.x) b1s[t] = b1[t];
    __syncthreads();
    float xbv = (tid < out_c) ? __half2float(Gs[HH * out_c + tid]) : 0.f;

    for (int base = 0; base < d; base += 8) {
        int m = min(8, d - base);
        __syncthreads();
        if (tid < m) eS[tid] = g_bucket[n * CAP + base + tid];
        __syncthreads();
        for (int t = tid; t < m * EF; t += blockDim.x)
            eas[t >> 3][t & 7] = ea[eS[t >> 3] * EF + (t & 7)];
        __syncthreads();
        int k = tid;
        if (k < HH) {
            for (int j = 0; j < m; j++) {
                float s = b1s[k];
#pragma unroll
                for (int q = 0; q < EF; q++) s = fmaf(eas[j][q], w1s[q][k], s);
                hs[j][k] = fmaxf(s, 0.f);
            }
        }
        __syncthreads();
        int o = tid;
        if (o < out_c) {
            float acc[8];
#pragma unroll
            for (int j = 0; j < 8; j++) acc[j] = 0.f;
            for (int kk = 0; kk < HH; kk++) {
                float g = __half2float(Gs[kk * out_c + o]);
#pragma unroll
                for (int j = 0; j < 8; j++) acc[j] = fmaf(hs[j][kk], g, acc[j]);
            }
            for (int j = 0; j < m; j++)
                msg[(size_t)eS[j] * out_c + o] = acc[j] + xbv;
        }
    }
}

// src-overflow fallback (normally zero iterations)
__global__ void msg_ovfS(const int* __restrict__ ei, const float* __restrict__ ea,
                         const float* __restrict__ w1, const float* __restrict__ b1,
                         int out_c, int strideG,
                         const __half* __restrict__ G, float* __restrict__ msg) {
    __shared__ float hs[HH];
    for (int idx = blockIdx.x; idx < g_ovfnS; idx += gridDim.x) {
        int e = g_ovfS[idx];
        int n = ei[e];
        int k = threadIdx.x;
        if (k < HH) {
            float s = b1[k];
#pragma unroll
            for (int q = 0; q < EF; q++) s = fmaf(ea[e * EF + q], w1[q * HH + k], s);
            hs[k] = fmaxf(s, 0.f);
        }
        __syncthreads();
        const __half* Grow = &G[(size_t)n * strideG];
        int o = threadIdx.x;
        if (o < out_c) {
            float acc = __half2float(Grow[HH * out_c + o]);
            for (int kk = 0; kk < HH; kk++)
                acc = fmaf(hs[kk], __half2float(Grow[kk * out_c + o]), acc);
            msg[(size_t)e * out_c + o] = acc;
        }
        __syncthreads();
    }
}

// dst-overflow fallback (normally zero iterations)
__global__ void agg_ovfD(const int* __restrict__ ei, int out_c,
                         const float* __restrict__ msg, float* __restrict__ agg) {
    for (int idx = blockIdx.x; idx < g_ovfnD; idx += gridDim.x) {
        int e = g_ovfD[idx];
        int t = ei[N_EDGES + e];
        int o = threadIdx.x;
        if (o < out_c) atomicAdd(&agg[t * out_c + o], msg[(size_t)e * out_c + o]);
    }
}

// per-dst-node: gather msgs + root + bias + relu (fused finalize; optional pool)
__global__ void aggfin(const float* __restrict__ Xin, float* __restrict__ Xout,
                       const float* __restrict__ root, const float* __restrict__ bias,
                       const float* __restrict__ agg, const float* __restrict__ msg,
                       int in_c, int out_c,
                       const int* __restrict__ batch, float* __restrict__ pool) {
    int n = blockIdx.x;
    __shared__ float xs[HH];
    __shared__ int eS[CAP];
    int tid = threadIdx.x;
    for (int t = tid; t < in_c; t += blockDim.x) xs[t] = Xin[n * in_c + t];
    int d = g_deg2[n];
    if (d > CAP) d = CAP;
    for (int t = tid; t < d; t += blockDim.x) eS[t] = g_bucket2[n * CAP + t];
    __syncthreads();
    int o = tid;
    if (o < out_c) {
        float acc = agg[n * out_c + o] + bias[o];
        for (int j = 0; j < d; j++)
            acc += msg[(size_t)eS[j] * out_c + o];
        for (int i = 0; i < in_c; i++)
            acc = fmaf(xs[i], __ldg(&root[i * out_c + o]), acc);
        acc = fmaxf(acc, 0.f);
        if (pool) atomicAdd(&pool[batch[n] * out_c + o], acc);
        else      Xout[n * out_c + o] = acc;
    }
}

__global__ void head_k(const float* __restrict__ fc1w, const float* __restrict__ fc1b,
                       const float* __restrict__ outw, const float* __restrict__ outb,
                       float* __restrict__ out) {
    int g = blockIdx.x;
    __shared__ float ps[H2];
    __shared__ float fs[HH];
    for (int t = threadIdx.x; t < H2; t += blockDim.x) ps[t] = g_pool[g * H2 + t];
    __syncthreads();
    int o = threadIdx.x;
    if (o < HH) {
        float a = fc1b[o];
        for (int i = 0; i < H2; i++) a = fmaf(ps[i], fc1w[i * HH + o], a);
        fs[o] = fmaxf(a, 0.f);
    }
    __syncthreads();
    if (threadIdx.x == 0) {
        float s = outb[0];
        for (int q = 0; q < HH; q++) s = fmaf(fs[q], outw[q], s);
        out[g] = s;
    }
}

// ---------------- host orchestration ----------------
static void run_layer(const float* Xin, float* Xout, int in_c, int out_c,
                      const float* w1, const float* b1, const float* w2, const float* b2,
                      const float* root, const float* bias,
                      const float* ea, const int* ei,
                      __half* G, __half* Ah, __half* BTh, float* agg, float* msg,
                      const int* batch, float* pool) {
    int ncp = (HH * out_c + out_c + 127) & ~127;   // 8192 / 8192 / 4096
    int kp = ((in_c + 31) & ~31);                  // 32 / 96 / 96
    int lda = kp + 8;

    padX<<<(N_NODES * kp + 255) / 256, 256>>>(Xin, Ah, in_c, kp);
    buildBT<<<(ncp * kp + 255) / 256, 256>>>(w2, b2, BTh, in_c, out_c, ncp, kp);
    {
        dim3 gr(ncp / 128, N_NODES / 128);
        size_t smem = (size_t)2 * 128 * lda * sizeof(__half);
        mma_gemm_h<<<gr, 256, smem>>>(Ah, BTh, G, ncp, kp, lda);
    }
    msg2<<<N_NODES, 96>>>(ei, ea, w1, b1, out_c, ncp, G, msg);
    msg_ovfS<<<64, 96>>>(ei, ea, w1, b1, out_c, ncp, G, msg);
    zero_f<<<(N_NODES * out_c + 255) / 256, 256>>>(agg, N_NODES * out_c);
    agg_ovfD<<<64, 96>>>(ei, out_c, msg, agg);
    aggfin<<<N_NODES, 96>>>(Xin, Xout, root, bias, agg, msg, in_c, out_c, batch, pool);
}

extern "C" void kernel_launch(void* const* d_in, const int* in_sizes, int n_in,
                              void* d_out, int out_size) {
    const float* x    = (const float*)d_in[0];
    const float* pos  = (const float*)d_in[1];
    const float* ea   = (const float*)d_in[2];
    const int*   ei   = (const int*)  d_in[3];
    const int*   bat  = (const int*)  d_in[4];
    const float* c1w1 = (const float*)d_in[5];
    const float* c1b1 = (const float*)d_in[6];
    const float* c1w2 = (const float*)d_in[7];
    const float* c1b2 = (const float*)d_in[8];
    const float* c1r  = (const float*)d_in[9];
    const float* c1b  = (const float*)d_in[10];
    const float* c2w1 = (const float*)d_in[11];
    const float* c2b1 = (const float*)d_in[12];
    const float* c2w2 = (const float*)d_in[13];
    const float* c2b2 = (const float*)d_in[14];
    const float* c2r  = (const float*)d_in[15];
    const float* c2b  = (const float*)d_in[16];
    const float* c3w1 = (const float*)d_in[17];
    const float* c3b1 = (const float*)d_in[18];
    const float* c3w2 = (const float*)d_in[19];
    const float* c3b2 = (const float*)d_in[20];
    const float* c3r  = (const float*)d_in[21];
    const float* c3b  = (const float*)d_in[22];
    const float* f1w  = (const float*)d_in[23];
    const float* f1b  = (const float*)d_in[24];
    const float* ow   = (const float*)d_in[25];
    const float* ob   = (const float*)d_in[26];
    float* out = (float*)d_out;

    cudaFuncSetAttribute(mma_gemm_h, cudaFuncAttributeMaxDynamicSharedMemorySize,
                         2 * 128 * (KP_MAX + 8) * (int)sizeof(__half));

    void *pX0, *pA, *pB, *pG, *pAh, *pBTh, *pagg, *pmsg, *ppool;
    cudaGetSymbolAddress(&pX0, g_X0);
    cudaGetSymbolAddress(&pA, g_bufA);
    cudaGetSymbolAddress(&pB, g_bufB);
    cudaGetSymbolAddress(&pG, g_G);
    cudaGetSymbolAddress(&pAh, g_Ah);
    cudaGetSymbolAddress(&pBTh, g_BTh);
    cudaGetSymbolAddress(&pagg, g_agg);
    cudaGetSymbolAddress(&pmsg, g_msg);
    cudaGetSymbolAddress(&ppool, g_pool);
    float* X0  = (float*)pX0;
    float* bufA= (float*)pA;
    float* bufB= (float*)pB;
    __half* G  = (__half*)pG;
    __half* Ah = (__half*)pAh;
    __half* BTh= (__half*)pBTh;
    float* agg = (float*)pagg;
    float* msg = (float*)pmsg;
    float* pool= (float*)ppool;

    build_x0<<<(N_NODES * F0 + 255) / 256, 256>>>(x, pos);
    init_deg<<<(N_NODES + 255) / 256, 256>>>();
    bucket_build<<<(N_EDGES + 255) / 256, 256>>>(ei);
    zero_f<<<(NGR * H2 + 255) / 256, 256>>>(pool, NGR * H2);

    // layer 1: 16 -> 90
    run_layer(X0, bufA, F0, HH, c1w1, c1b1, c1w2, c1b2, c1r, c1b, ea, ei,
              G, Ah, BTh, agg, msg, nullptr, nullptr);
    // layer 2: 90 -> 90
    run_layer(bufA, bufB, HH, HH, c2w1, c2b1, c2w2, c2b2, c2r, c2b, ea, ei,
              G, Ah, BTh, agg, msg, nullptr, nullptr);
    // layer 3: 90 -> 45, fused global_add_pool
    run_layer(bufB, bufA, HH, H2, c3w1, c3b1, c3w2, c3b2, c3r, c3b, ea, ei,
              G, Ah, BTh, agg, msg, bat, pool);

    head_k<<<NGR, 96>>>(f1w, f1b, ow, ob, out);
}